// round 13
// baseline (speedup 1.0000x reference)
#include <cuda_runtime.h>
#include <cuda_bf16.h>
#include <math.h>
#include <stdint.h>

#define T_STEPS 512
#define BATCH   128
#define IN_DIM  64
#define HID     1024
#define OUT_DIM 64
#define GATES   (3 * HID)
#define MROWS   (T_STEPS * BATCH)   // 65536
#define NBLK    128
#define RTHR    512

typedef unsigned long long u64;

// Persistent scratch (device globals -- no allocation anywhere).
__device__ float g_gi[(size_t)MROWS * GATES];        // input-side gates
__device__ float g_h1[(size_t)MROWS * HID];          // layer outputs (fp32)
__device__ __nv_bfloat16 g_h1hi[(size_t)MROWS * HID];// layer outputs, bf16 hi plane
__device__ __nv_bfloat16 g_h1lo[(size_t)MROWS * HID];// layer outputs, bf16 lo plane
__device__ __nv_bfloat16 g_hzero[BATCH * HID];       // zeros (h_{-1})
__device__ __nv_bfloat16 g_wbhi[(size_t)HID * GATES];// w_ih1 transposed [k][n], hi
__device__ __nv_bfloat16 g_wblo[(size_t)HID * GATES];// lo
__device__ unsigned g_bar_gen;
__device__ unsigned g_bar_cnt;

// ---------- helpers ----------
__device__ __forceinline__ void fma2(u64 &d, u64 a, u64 b) {
    asm("fma.rn.f32x2 %0, %1, %2, %0;" : "+l"(d) : "l"(a), "l"(b));
}
__device__ __forceinline__ u64 dup2(float x) {
    u64 r; asm("mov.b64 %0, {%1, %1};" : "=l"(r) : "f"(x)); return r;
}
__device__ __forceinline__ float2 unpk(u64 v) {
    float2 r; asm("mov.b64 {%0, %1}, %2;" : "=f"(r.x), "=f"(r.y) : "l"(v)); return r;
}
__device__ __forceinline__ float4 ldcg_f32x4(const void* p) {
    float4 v;
    asm volatile("ld.global.cg.v4.f32 {%0, %1, %2, %3}, [%4];"
                 : "=f"(v.x), "=f"(v.y), "=f"(v.z), "=f"(v.w) : "l"(p));
    return v;
}
__device__ __forceinline__ float ldcg_f32(const void* p) {
    float v;
    asm volatile("ld.global.cg.f32 %0, [%1];" : "=f"(v) : "l"(p));
    return v;
}
__device__ __forceinline__ void cp16(unsigned d, const void* s) {
    asm volatile("cp.async.cg.shared.global [%0], [%1], 16;" :: "r"(d), "l"(s));
}
__device__ __forceinline__ void ldsm4(uint32_t* r, uint32_t a) {
    asm volatile("ldmatrix.sync.aligned.m8n8.x4.shared.b16 {%0,%1,%2,%3}, [%4];"
                 : "=r"(r[0]), "=r"(r[1]), "=r"(r[2]), "=r"(r[3]) : "r"(a));
}
__device__ __forceinline__ void ldsm2t(uint32_t* r, uint32_t a) {
    asm volatile("ldmatrix.sync.aligned.m8n8.x2.trans.shared.b16 {%0,%1}, [%2];"
                 : "=r"(r[0]), "=r"(r[1]) : "r"(a));
}
__device__ __forceinline__ void mma16816(float* c, const uint32_t* a, const uint32_t* b) {
    asm volatile("mma.sync.aligned.m16n8k16.row.col.f32.bf16.bf16.f32 "
                 "{%0,%1,%2,%3}, {%4,%5,%6,%7}, {%8,%9}, {%0,%1,%2,%3};"
                 : "+f"(c[0]), "+f"(c[1]), "+f"(c[2]), "+f"(c[3])
                 : "r"(a[0]), "r"(a[1]), "r"(a[2]), "r"(a[3]), "r"(b[0]), "r"(b[1]));
}
// swizzles (byte-offset XOR)
__device__ __forceinline__ uint32_t SWA(uint32_t a) { return a ^ ((a >> 3) & 0x10); }  // 32B rows
__device__ __forceinline__ uint32_t SWR(int row, uint32_t c) { return c ^ (((uint32_t)row & 7u) << 4); }

// ---- grid barrier: release/acquire, nanosleep poll ----
__device__ __forceinline__ void grid_bar() {
    __syncthreads();
    if (threadIdx.x == 0) {
        unsigned gen;
        asm volatile("ld.global.relaxed.gpu.u32 %0, [%1];"
                     : "=r"(gen) : "l"(&g_bar_gen));
        asm volatile("fence.acq_rel.gpu;" ::: "memory");
        unsigned prev = atomicAdd(&g_bar_cnt, 1u);
        if (prev == (unsigned)(NBLK - 1)) {
            asm volatile("st.global.relaxed.gpu.u32 [%0], %1;"
                         :: "l"(&g_bar_cnt), "r"(0u) : "memory");
            asm volatile("fence.acq_rel.gpu;" ::: "memory");
            asm volatile("st.global.relaxed.gpu.u32 [%0], %1;"
                         :: "l"(&g_bar_gen), "r"(gen + 1u) : "memory");
        } else {
            unsigned cur;
            do {
                __nanosleep(64);
                asm volatile("ld.global.relaxed.gpu.u32 %0, [%1];"
                             : "=r"(cur) : "l"(&g_bar_gen));
            } while (cur == gen);
            asm volatile("fence.acq_rel.gpu;" ::: "memory");
        }
    }
    __syncthreads();
}

// rec smem layout (bytes)
#define SMEM_BIAS 0                       // 64 floats
#define SMEM_W    1024                    // 2 grp x (hi 48K + lo 48K) = 192 KB
#define WGRP      98304
#define WLO_OFF   49152
#define SMEM_ACT  (1024 + 2 * WGRP)       // 197632: 4 bufs x 8 KB
#define ABUF      8192                    // [2 pl][64 rows][64 B (32 k)], seg-XOR
#define SMEM_TOT  (SMEM_ACT + 4 * ABUF)   // 230,400 B
// red buffer (24,576 B) aliases SMEM_ACT after the k-loop.

// ============================================================================
// GRU recurrence on mma.sync, batch-split blocking: block (bm = bid&1,
// bj = bid>>1) owns m in [64bm, 64bm+64) x 16 units (2 groups of 8).
// Block-shared k32 chunk staging (coalesced), ring 4, distance 3.
// Warp (p = wid&3: m16, r = (wid>>2)&1: unit group, q = wid>>3: k16-half).
// 3-product bf16 split throughout (hi*hi + lo*hi + hi*lo).
// ============================================================================
__global__ void __launch_bounds__(RTHR, 1)
gru_rec_mma(const float* __restrict__ w_hh, const float* __restrict__ b_ih,
            const float* __restrict__ b_hh)
{
    extern __shared__ char smem[];
    const int tid  = threadIdx.x;
    const int wid  = tid >> 5;
    const int lane = tid & 31;
    const int bid  = blockIdx.x;
    const int bm   = bid & 1;
    const int bj   = bid >> 1;
    const int m0   = bm * 64;
    const int j0   = bj * 16;
    const int p    = wid & 3;
    const int r    = (wid >> 2) & 1;
    const int q    = wid >> 3;
    const uint32_t sb = (uint32_t)__cvta_generic_to_shared(smem);

    // persistent W hi/lo: per group [1024 k][24 n], 48B rows
    for (int idx = tid; idx < 48 * HID; idx += RTHR) {
        int n48 = idx >> 10, k = idx & 1023;
        int grp = n48 / 24, nn = n48 % 24;
        int g = nn >> 3, uu = nn & 7;
        float w = w_hh[((size_t)g * HID + j0 + grp * 8 + uu) * HID + k];
        __nv_bfloat16 hi = __float2bfloat16(w);
        __nv_bfloat16 lo = __float2bfloat16(w - __bfloat162float(hi));
        uint32_t a = (uint32_t)(SMEM_W + grp * WGRP + k * 48 + nn * 2);
        *(__nv_bfloat16*)(smem + a)           = hi;
        *(__nv_bfloat16*)(smem + a + WLO_OFF) = lo;
    }
    if (tid < 16) {
        float* sB = (float*)(smem + SMEM_BIAS);
        int j = j0 + tid;
        sB[tid]      = b_ih[j] + b_hh[j];                    // r
        sB[16 + tid] = b_ih[HID + j] + b_hh[HID + j];        // z
        sB[32 + tid] = b_ih[2 * HID + j];                    // in
        sB[48 + tid] = b_hh[2 * HID + j];                    // hn
    }
    for (int idx = bid * RTHR + tid; idx < BATCH * HID; idx += NBLK * RTHR)
        g_hzero[idx] = __float2bfloat16(0.0f);
    __syncthreads();
    grid_bar();

    // lane-constant maps
    const int relrow = ((lane >> 3) & 1) * 8 + (lane & 7);
    const int segA   = lane >> 4;
    const int arow   = p * 16 + relrow;
    const uint32_t offA = (uint32_t)(arow * 64)
                        + (uint32_t)(((q * 2 + segA) ^ (arow & 3)) * 16);
    const int rbB = lane & 15;
    // coalesced staging map: 4 lanes cover one 64B row segment
    const int spl   = tid >> 8;          // plane: 0 = hi, 1 = lo
    const int sidx  = tid & 255;
    const int srow  = sidx >> 2;         // 0..63
    const int sseg  = sidx & 3;          // 16B seg within 64B
    const uint32_t sdst = (uint32_t)(spl * 4096 + srow * 64
                        + ((sseg ^ (srow & 3)) * 16));
    const int eu = tid & 15;             // unit 0..15
    const int em = tid >> 4;             // m 0..31 (items em, em+32)
    const int e_ru = eu >> 3, e_uu = eu & 7;
    const int col_r = e_ru * 24 + e_uu;

    const uint32_t wbase = sb + (uint32_t)(SMEM_W + r * WGRP);

    for (int t = 0; t < T_STEPS; ++t) {
        const __nv_bfloat16* hi_src = t ? g_h1hi + (size_t)(t - 1) * BATCH * HID : g_hzero;
        const __nv_bfloat16* lo_src = t ? g_h1lo + (size_t)(t - 1) * BATCH * HID : g_hzero;
        const __nv_bfloat16* splane = (spl ? lo_src : hi_src) + (size_t)(m0 + srow) * HID;

        // prologue: stage chunks 0..2 into bufs 0..2
        #pragma unroll
        for (int pre = 0; pre < 3; ++pre) {
            cp16(sb + (uint32_t)(SMEM_ACT + pre * ABUF) + sdst,
                 splane + pre * 32 + sseg * 8);
            asm volatile("cp.async.commit_group;");
        }

        // epilogue operand prefetch
        float gir[2], giz[2], gin[2], hpv[2];
        #pragma unroll
        for (int it = 0; it < 2; ++it) {
            int m = m0 + em + it * 32;
            const float* gp = g_gi + ((size_t)t * BATCH + m) * GATES + j0 + eu;
            gir[it] = ldcg_f32(gp);
            giz[it] = ldcg_f32(gp + HID);
            gin[it] = ldcg_f32(gp + 2 * HID);
            hpv[it] = t ? ldcg_f32(g_h1 + ((size_t)(t - 1) * BATCH + m) * HID + j0 + eu)
                        : 0.0f;
        }

        float c[3][4];
        #pragma unroll
        for (int g = 0; g < 3; ++g)
            #pragma unroll
            for (int x = 0; x < 4; ++x) c[g][x] = 0.0f;

        #pragma unroll 1
        for (int i = 0; i < 32; ++i) {
            __syncthreads();   // all warps done with the buffer chunk i+3 reuses
            if (i + 3 < 32) {
                cp16(sb + (uint32_t)(SMEM_ACT + ((i + 3) & 3) * ABUF) + sdst,
                     splane + (i + 3) * 32 + sseg * 8);
                asm volatile("cp.async.commit_group;");
                asm volatile("cp.async.wait_group 3;");
            } else {
                asm volatile("cp.async.wait_group 0;");
            }
            __syncthreads();   // chunk i visible

            const int kb = i * 32 + q * 16;
            uint32_t bh[3][2], bl[3][2];
            #pragma unroll
            for (int g = 0; g < 3; ++g) {
                uint32_t a = (uint32_t)((kb + rbB) * 48 + g * 16);
                ldsm2t(bh[g], wbase + a);
                ldsm2t(bl[g], wbase + WLO_OFF + a);
            }
            const uint32_t abase = sb + (uint32_t)(SMEM_ACT + (i & 3) * ABUF);
            uint32_t ah[4], al[4];
            ldsm4(ah, abase + offA);
            ldsm4(al, abase + 4096 + offA);
            #pragma unroll
            for (int g = 0; g < 3; ++g) {
                mma16816(c[g], ah, bh[g]);
                mma16816(c[g], al, bh[g]);
                mma16816(c[g], ah, bl[g]);
            }
        }

        __syncthreads();   // act bufs idle; red aliases them
        float* red = (float*)(smem + SMEM_ACT);   // [64 m][48 n][2 q]
        {
            const int rr = p * 16 + (lane >> 2);
            const int c2 = (lane & 3) * 2;
            #pragma unroll
            for (int g = 0; g < 3; ++g) {
                int nn = r * 24 + g * 8 + c2;
                red[((size_t)rr * 48 + nn) * 2 + q]           = c[g][0];
                red[((size_t)rr * 48 + nn + 1) * 2 + q]       = c[g][1];
                red[((size_t)(rr + 8) * 48 + nn) * 2 + q]     = c[g][2];
                red[((size_t)(rr + 8) * 48 + nn + 1) * 2 + q] = c[g][3];
            }
        }
        __syncthreads();

        {
            const float* sB = (const float*)(smem + SMEM_BIAS);
            #pragma unroll
            for (int it = 0; it < 2; ++it) {
                int ml = em + it * 32;           // local m
                int m  = m0 + ml;                // global m
                float2 vr = *(const float2*)(red + ((size_t)ml * 48 + col_r) * 2);
                float2 vz = *(const float2*)(red + ((size_t)ml * 48 + col_r + 8) * 2);
                float2 vn = *(const float2*)(red + ((size_t)ml * 48 + col_r + 16) * 2);
                float ghr = vr.x + vr.y;
                float ghz = vz.x + vz.y;
                float ghn = vn.x + vn.y;
                float rg = 1.0f / (1.0f + expf(-(gir[it] + ghr + sB[eu])));
                float zg = 1.0f / (1.0f + expf(-(giz[it] + ghz + sB[16 + eu])));
                float ng = tanhf(gin[it] + sB[32 + eu] + rg * (ghn + sB[48 + eu]));
                float h  = (1.0f - zg) * ng + zg * hpv[it];

                __nv_bfloat16 hi = __float2bfloat16(h);
                __nv_bfloat16 lo = __float2bfloat16(h - __bfloat162float(hi));
                size_t o = ((size_t)t * BATCH + m) * HID + j0 + eu;
                g_h1hi[o] = hi;
                g_h1lo[o] = lo;
                g_h1[o]   = h;
            }
        }

        grid_bar();
    }
}

// ============================================================================
// Transpose + bf16-split w_ih1: [3072 n][1024 k] fp32 -> [k][n] hi/lo planes.
// ============================================================================
__global__ void __launch_bounds__(256)
conv_w(const float* __restrict__ w)
{
    __shared__ float tile[32][33];
    const int tx = threadIdx.x & 31;
    const int ty = threadIdx.x >> 5;
    const int k0 = blockIdx.x * 32;
    const int n0 = blockIdx.y * 32;
    #pragma unroll
    for (int r = 0; r < 4; ++r)
        tile[ty + r * 8][tx] = w[(size_t)(n0 + ty + r * 8) * HID + k0 + tx];
    __syncthreads();
    #pragma unroll
    for (int r = 0; r < 4; ++r) {
        float v = tile[tx][ty + r * 8];
        __nv_bfloat16 hi = __float2bfloat16(v);
        __nv_bfloat16 lo = __float2bfloat16(v - __bfloat162float(hi));
        size_t o = (size_t)(k0 + ty + r * 8) * GATES + n0 + tx;
        g_wbhi[o] = hi;
        g_wblo[o] = lo;
    }
}

// ============================================================================
// gi1 = h1 @ w_ih1^T on mma.sync (bf16 3-split). Tile 128m x 128n, K=1024.
// Stage = A[2pl][128m][32B] (8KB, SWA) + B[2pl][16k][256B] (8KB, SWR) = 16KB.
// 4-deep ring in dynamic smem (64 KB). 512 thr: tid<256 stage A, >=256 stage B.
// ============================================================================
#define GST 16384
__global__ void __launch_bounds__(512)
gemm_bf16_3s(float* __restrict__ C)
{
    extern __shared__ char gsm[];   // 4 * 16384
    const int tid  = threadIdx.x;
    const int wid  = tid >> 5;
    const int lane = tid & 31;
    const int m0 = blockIdx.y * 128;
    const int n0 = blockIdx.x * 128;
    const int p  = wid & 3;
    const int nq = wid >> 2;
    const uint32_t sb = (uint32_t)__cvta_generic_to_shared(gsm);

    const int relrow = ((lane >> 3) & 1) * 8 + (lane & 7);
    const int segA   = lane >> 4;
    const uint32_t offA0 = SWA((uint32_t)((p * 32 + relrow) * 32 + segA * 16));
    const uint32_t offA1 = SWA((uint32_t)((p * 32 + 16 + relrow) * 32 + segA * 16));
    const int rbB = lane & 15;
    uint32_t offB[4];
    #pragma unroll
    for (int nt = 0; nt < 4; ++nt)
        offB[nt] = (uint32_t)(8192 + rbB * 256) + SWR(rbB, (uint32_t)(nq * 64 + nt * 16));

    // staging maps
    const bool stA = (tid < 256);
    const int  apl = (tid >> 7) & 1;
    const int  am  = tid & 127;
    const int  bix = tid & 255;
    const int  bpl = bix >> 7;
    const int  brw = (bix & 127) >> 3;
    const int  bcs = (bix & 7) * 32;

    const __nv_bfloat16* Asrc = (apl ? g_h1lo : g_h1hi) + (size_t)(m0 + am) * HID;
    const __nv_bfloat16* Bpl  = (bpl ? g_wblo : g_wbhi) + n0 + bcs / 2;
    const uint32_t adst0 = (uint32_t)(apl * 4096) + SWA((uint32_t)(am * 32));
    const uint32_t adst1 = (uint32_t)(apl * 4096) + SWA((uint32_t)(am * 32 + 16));
    const uint32_t bdst0 = (uint32_t)(8192 + bpl * 4096 + brw * 256)
                         + SWR(brw, (uint32_t)bcs);
    const uint32_t bdst1 = (uint32_t)(8192 + bpl * 4096 + brw * 256)
                         + SWR(brw, (uint32_t)(bcs + 16));

    float c[2][4][4];
    #pragma unroll
    for (int mt = 0; mt < 2; ++mt)
        #pragma unroll
        for (int nt = 0; nt < 4; ++nt)
            #pragma unroll
            for (int x = 0; x < 4; ++x) c[mt][nt][x] = 0.0f;

    #pragma unroll
    for (int pre = 0; pre < 3; ++pre) {
        uint32_t base = sb + (uint32_t)(pre * GST);
        if (stA) {
            cp16(base + adst0, Asrc + pre * 16);
            cp16(base + adst1, Asrc + pre * 16 + 8);
        } else {
            const __nv_bfloat16* s = Bpl + (size_t)(pre * 16 + brw) * GATES;
            cp16(base + bdst0, s);
            cp16(base + bdst1, s + 8);
        }
        asm volatile("cp.async.commit_group;");
    }

    #pragma unroll 1
    for (int i = 0; i < 64; ++i) {
        __syncthreads();
        if (i + 3 < 64) {
            uint32_t base = sb + (uint32_t)(((i + 3) & 3) * GST);
            if (stA) {
                cp16(base + adst0, Asrc + (i + 3) * 16);
                cp16(base + adst1, Asrc + (i + 3) * 16 + 8);
            } else {
                const __nv_bfloat16* s = Bpl + (size_t)((i + 3) * 16 + brw) * GATES;
                cp16(base + bdst0, s);
                cp16(base + bdst1, s + 8);
            }
            asm volatile("cp.async.commit_group;");
            asm volatile("cp.async.wait_group 3;");
        } else {
            asm volatile("cp.async.wait_group 0;");
        }
        __syncthreads();

        const uint32_t base = sb + (uint32_t)((i & 3) * GST);
        uint32_t bh[4][2], bl[4][2];
        #pragma unroll
        for (int nt = 0; nt < 4; ++nt) {
            ldsm2t(bh[nt], base + offB[nt]);
            ldsm2t(bl[nt], base + offB[nt] + 4096);
        }
        #pragma unroll
        for (int mt = 0; mt < 2; ++mt) {
            uint32_t off = mt ? offA1 : offA0;
            uint32_t ah[4], al[4];
            ldsm4(ah, base + off);
            ldsm4(al, base + 4096 + off);
            #pragma unroll
            for (int nt = 0; nt < 4; ++nt) {
                mma16816(c[mt][nt], ah, bh[nt]);
                mma16816(c[mt][nt], al, bh[nt]);
                mma16816(c[mt][nt], ah, bl[nt]);
            }
        }
    }

    #pragma unroll
    for (int mt = 0; mt < 2; ++mt) {
        int row = m0 + p * 32 + mt * 16 + (lane >> 2);
        #pragma unroll
        for (int nt = 0; nt < 4; ++nt) {
            int col = n0 + nq * 32 + nt * 8 + (lane & 3) * 2;
            *(float2*)(C + (size_t)row * GATES + col) =
                make_float2(c[mt][nt][0], c[mt][nt][1]);
            *(float2*)(C + (size_t)(row + 8) * GATES + col) =
                make_float2(c[mt][nt][2], c[mt][nt][3]);
        }
    }
}

// ============================================================================
// gi0 = x @ w_ih0^T  (K=64, fp32 f32x2)
// ============================================================================
#define GKC 16
__global__ void __launch_bounds__(256)
gemm_tn_f32x2(const float* __restrict__ A, const float* __restrict__ B,
              float* __restrict__ C, int M, int N, int K)
{
    __shared__ float sA[GKC][132];
    __shared__ float sB[GKC][132];
    const int tid = threadIdx.x;
    const int m0  = blockIdx.y * 128;
    const int n0  = blockIdx.x * 128;
    const int ty  = tid >> 4, tx = tid & 15;
    const int sr = tid >> 1;
    const int sk = (tid & 1) * 8;

    u64 acc[4][8];
    #pragma unroll
    for (int p = 0; p < 4; ++p)
        #pragma unroll
        for (int c = 0; c < 8; ++c) acc[p][c] = 0ull;

    const float* Ag = A + (size_t)(m0 + sr) * K + sk;
    const float* Bg = B + (size_t)(n0 + sr) * K + sk;
    float4 a0 = ldcg_f32x4(Ag);
    float4 a1 = ldcg_f32x4(Ag + 4);
    float4 b0 = ldcg_f32x4(Bg);
    float4 b1 = ldcg_f32x4(Bg + 4);

    for (int kc = 0; kc < K; kc += GKC) {
        sA[sk + 0][sr] = a0.x; sA[sk + 1][sr] = a0.y;
        sA[sk + 2][sr] = a0.z; sA[sk + 3][sr] = a0.w;
        sA[sk + 4][sr] = a1.x; sA[sk + 5][sr] = a1.y;
        sA[sk + 6][sr] = a1.z; sA[sk + 7][sr] = a1.w;
        sB[sk + 0][sr] = b0.x; sB[sk + 1][sr] = b0.y;
        sB[sk + 2][sr] = b0.z; sB[sk + 3][sr] = b0.w;
        sB[sk + 4][sr] = b1.x; sB[sk + 5][sr] = b1.y;
        sB[sk + 6][sr] = b1.z; sB[sk + 7][sr] = b1.w;
        if (kc + GKC < K) {
            Ag += GKC; Bg += GKC;
            a0 = ldcg_f32x4(Ag);
            a1 = ldcg_f32x4(Ag + 4);
            b0 = ldcg_f32x4(Bg);
            b1 = ldcg_f32x4(Bg + 4);
        }
        __syncthreads();
        #pragma unroll
        for (int kk = 0; kk < GKC; ++kk) {
            ulonglong2 aa = *(const ulonglong2*)(&sA[kk][ty * 8]);
            ulonglong2 ab = *(const ulonglong2*)(&sA[kk][ty * 8 + 4]);
            float4 bv0 = *(const float4*)(&sB[kk][tx * 8]);
            float4 bv1 = *(const float4*)(&sB[kk][tx * 8 + 4]);
            float bs[8] = {bv0.x, bv0.y, bv0.z, bv0.w, bv1.x, bv1.y, bv1.z, bv1.w};
            #pragma unroll
            for (int c = 0; c < 8; ++c) {
                u64 bd = dup2(bs[c]);
                fma2(acc[0][c], aa.x, bd);
                fma2(acc[1][c], aa.y, bd);
                fma2(acc[2][c], ab.x, bd);
                fma2(acc[3][c], ab.y, bd);
            }
        }
        __syncthreads();
    }

    #pragma unroll
    for (int p = 0; p < 4; ++p) {
        float2 v[8];
        #pragma unroll
        for (int c = 0; c < 8; ++c) v[c] = unpk(acc[p][c]);
        int row0 = m0 + ty * 8 + p * 2;
        float* c0 = C + (size_t)row0 * N + n0 + tx * 8;
        float* c1 = c0 + N;
        *(float4*)(c0)     = make_float4(v[0].x, v[1].x, v[2].x, v[3].x);
        *(float4*)(c0 + 4) = make_float4(v[4].x, v[5].x, v[6].x, v[7].x);
        *(float4*)(c1)     = make_float4(v[0].y, v[1].y, v[2].y, v[3].y);
        *(float4*)(c1 + 4) = make_float4(v[4].y, v[5].y, v[6].y, v[7].y);
    }
}

// ============================================================================
// out[t,b,o] = h2[t,b,:] . w_lin[o,:] + b_lin[o]  (h2 in g_h1)
// ============================================================================
__global__ void __launch_bounds__(256)
out_linear(const float* __restrict__ w_lin, const float* __restrict__ b_lin,
           float* __restrict__ out)
{
    __shared__ float sA[16][68];
    __shared__ float sB[16][68];
    const int tid = threadIdx.x;
    const size_t rb = (size_t)blockIdx.x * 64;
    const int ty = tid >> 4;
    const int tx = tid & 15;
    const int li   = tid * 4;
    const int srow = li >> 4;
    const int skk  = li & 15;

    float acc[4][4] = {};

    for (int kc = 0; kc < HID; kc += 16) {
        __syncthreads();
        float4 va = ldcg_f32x4(g_h1 + (rb + srow) * HID + kc + skk);
        sA[skk + 0][srow] = va.x; sA[skk + 1][srow] = va.y;
        sA[skk + 2][srow] = va.z; sA[skk + 3][srow] = va.w;
        float4 vb = *(const float4*)(w_lin + (size_t)srow * HID + kc + skk);
        sB[skk + 0][srow] = vb.x; sB[skk + 1][srow] = vb.y;
        sB[skk + 2][srow] = vb.z; sB[skk + 3][srow] = vb.w;
        __syncthreads();
        #pragma unroll
        for (int kk = 0; kk < 16; ++kk) {
            float4 a = *(const float4*)&sA[kk][ty * 4];
            float4 b = *(const float4*)&sB[kk][tx * 4];
            acc[0][0] = fmaf(a.x, b.x, acc[0][0]); acc[0][1] = fmaf(a.x, b.y, acc[0][1]);
            acc[0][2] = fmaf(a.x, b.z, acc[0][2]); acc[0][3] = fmaf(a.x, b.w, acc[0][3]);
            acc[1][0] = fmaf(a.y, b.x, acc[1][0]); acc[1][1] = fmaf(a.y, b.y, acc[1][1]);
            acc[1][2] = fmaf(a.y, b.z, acc[1][2]); acc[1][3] = fmaf(a.y, b.w, acc[1][3]);
            acc[2][0] = fmaf(a.z, b.x, acc[2][0]); acc[2][1] = fmaf(a.z, b.y, acc[2][1]);
            acc[2][2] = fmaf(a.z, b.z, acc[2][2]); acc[2][3] = fmaf(a.z, b.w, acc[2][3]);
            acc[3][0] = fmaf(a.w, b.x, acc[3][0]); acc[3][1] = fmaf(a.w, b.y, acc[3][1]);
            acc[3][2] = fmaf(a.w, b.z, acc[3][2]); acc[3][3] = fmaf(a.w, b.w, acc[3][3]);
        }
    }

    #pragma unroll
    for (int i = 0; i < 4; ++i) {
        float4 o4;
        o4.x = acc[i][0] + b_lin[tx * 4 + 0];
        o4.y = acc[i][1] + b_lin[tx * 4 + 1];
        o4.z = acc[i][2] + b_lin[tx * 4 + 2];
        o4.w = acc[i][3] + b_lin[tx * 4 + 3];
        *(float4*)(out + (rb + ty * 4 + i) * OUT_DIM + tx * 4) = o4;
    }
}

extern "C" void kernel_launch(void* const* d_in, const int* in_sizes, int n_in,
                              void* d_out, int out_size)
{
    const float* x     = (const float*)d_in[0];
    const float* w_ih0 = (const float*)d_in[1];
    const float* w_hh0 = (const float*)d_in[2];
    const float* b_ih0 = (const float*)d_in[3];
    const float* b_hh0 = (const float*)d_in[4];
    const float* w_ih1 = (const float*)d_in[5];
    const float* w_hh1 = (const float*)d_in[6];
    const float* b_ih1 = (const float*)d_in[7];
    const float* b_hh1 = (const float*)d_in[8];
    const float* w_lin = (const float*)d_in[9];
    const float* b_lin = (const float*)d_in[10];
    float* out = (float*)d_out;
    (void)in_sizes; (void)n_in; (void)out_size;

    float *gi_ptr;
    cudaGetSymbolAddress((void**)&gi_ptr, g_gi);

    cudaFuncSetAttribute(gru_rec_mma, cudaFuncAttributeMaxDynamicSharedMemorySize, SMEM_TOT);
    cudaFuncSetAttribute(gemm_bf16_3s, cudaFuncAttributeMaxDynamicSharedMemorySize, 4 * GST);

    // w_ih1 transpose + split (independent of layer 0)
    conv_w<<<dim3(HID / 32, GATES / 32), 256>>>(w_ih1);

    // layer 0
    gemm_tn_f32x2<<<dim3(GATES / 128, MROWS / 128), 256>>>(x, w_ih0, gi_ptr,
                                                           MROWS, GATES, IN_DIM);
    gru_rec_mma<<<NBLK, RTHR, SMEM_TOT>>>(w_hh0, b_ih0, b_hh0);

    // layer 1
    gemm_bf16_3s<<<dim3(GATES / 128, MROWS / 128), 512, 4 * GST>>>(gi_ptr);
    gru_rec_mma<<<NBLK, RTHR, SMEM_TOT>>>(w_hh1, b_ih1, b_hh1);

    // time-distributed linear
    out_linear<<<MROWS / 64, 256>>>(w_lin, b_lin, out);
}

// round 14
// speedup vs baseline: 1.2253x; 1.2253x over previous
#include <cuda_runtime.h>
#include <cuda_bf16.h>
#include <math.h>
#include <stdint.h>

#define T_STEPS 512
#define BATCH   128
#define IN_DIM  64
#define HID     1024
#define OUT_DIM 64
#define GATES   (3 * HID)
#define MROWS   (T_STEPS * BATCH)   // 65536
#define NBLK    128
#define RTHR    512

typedef unsigned long long u64;

// Persistent scratch (device globals -- no allocation anywhere).
__device__ float g_gi[(size_t)MROWS * GATES];        // input-side gates
__device__ float g_h1[(size_t)MROWS * HID];          // layer outputs (fp32)
__device__ __nv_bfloat16 g_h1hi[(size_t)MROWS * HID];// layer outputs, bf16 hi plane
__device__ __nv_bfloat16 g_h1lo[(size_t)MROWS * HID];// layer outputs, bf16 lo plane
__device__ __nv_bfloat16 g_hzero[BATCH * HID];       // zeros (h_{-1})
__device__ __nv_bfloat16 g_wbhi[(size_t)HID * GATES];// w_ih1 transposed [k][n], hi
__device__ __nv_bfloat16 g_wblo[(size_t)HID * GATES];// lo
__device__ unsigned g_bar_gen;
__device__ unsigned g_bar_cnt;

// ---------- helpers ----------
__device__ __forceinline__ void fma2(u64 &d, u64 a, u64 b) {
    asm("fma.rn.f32x2 %0, %1, %2, %0;" : "+l"(d) : "l"(a), "l"(b));
}
__device__ __forceinline__ u64 dup2(float x) {
    u64 r; asm("mov.b64 %0, {%1, %1};" : "=l"(r) : "f"(x)); return r;
}
__device__ __forceinline__ float2 unpk(u64 v) {
    float2 r; asm("mov.b64 {%0, %1}, %2;" : "=f"(r.x), "=f"(r.y) : "l"(v)); return r;
}
__device__ __forceinline__ float4 ldcg_f32x4(const void* p) {
    float4 v;
    asm volatile("ld.global.cg.v4.f32 {%0, %1, %2, %3}, [%4];"
                 : "=f"(v.x), "=f"(v.y), "=f"(v.z), "=f"(v.w) : "l"(p));
    return v;
}
__device__ __forceinline__ float ldcg_f32(const void* p) {
    float v;
    asm volatile("ld.global.cg.f32 %0, [%1];" : "=f"(v) : "l"(p));
    return v;
}
__device__ __forceinline__ void cp16(unsigned d, const void* s) {
    asm volatile("cp.async.cg.shared.global [%0], [%1], 16;" :: "r"(d), "l"(s));
}
__device__ __forceinline__ void ldsm4(uint32_t* r, uint32_t a) {
    asm volatile("ldmatrix.sync.aligned.m8n8.x4.shared.b16 {%0,%1,%2,%3}, [%4];"
                 : "=r"(r[0]), "=r"(r[1]), "=r"(r[2]), "=r"(r[3]) : "r"(a));
}
__device__ __forceinline__ void ldsm2t(uint32_t* r, uint32_t a) {
    asm volatile("ldmatrix.sync.aligned.m8n8.x2.trans.shared.b16 {%0,%1}, [%2];"
                 : "=r"(r[0]), "=r"(r[1]) : "r"(a));
}
__device__ __forceinline__ void mma16816(float* c, const uint32_t* a, const uint32_t* b) {
    asm volatile("mma.sync.aligned.m16n8k16.row.col.f32.bf16.bf16.f32 "
                 "{%0,%1,%2,%3}, {%4,%5,%6,%7}, {%8,%9}, {%0,%1,%2,%3};"
                 : "+f"(c[0]), "+f"(c[1]), "+f"(c[2]), "+f"(c[3])
                 : "r"(a[0]), "r"(a[1]), "r"(a[2]), "r"(a[3]), "r"(b[0]), "r"(b[1]));
}
// swizzles (byte-offset XOR)
__device__ __forceinline__ uint32_t SWA(uint32_t a) { return a ^ ((a >> 3) & 0x10); }   // 32B rows
__device__ __forceinline__ uint32_t SW128(uint32_t a){ return a ^ ((a >> 3) & 0x70); }  // 128B rows
__device__ __forceinline__ uint32_t SWR(int row, uint32_t c) { return c ^ (((uint32_t)row & 7u) << 4); }

// ---- grid barrier: release/acquire, nanosleep poll ----
__device__ __forceinline__ void grid_bar() {
    __syncthreads();
    if (threadIdx.x == 0) {
        unsigned gen;
        asm volatile("ld.global.relaxed.gpu.u32 %0, [%1];"
                     : "=r"(gen) : "l"(&g_bar_gen));
        asm volatile("fence.acq_rel.gpu;" ::: "memory");
        unsigned prev = atomicAdd(&g_bar_cnt, 1u);
        if (prev == (unsigned)(NBLK - 1)) {
            asm volatile("st.global.relaxed.gpu.u32 [%0], %1;"
                         :: "l"(&g_bar_cnt), "r"(0u) : "memory");
            asm volatile("fence.acq_rel.gpu;" ::: "memory");
            asm volatile("st.global.relaxed.gpu.u32 [%0], %1;"
                         :: "l"(&g_bar_gen), "r"(gen + 1u) : "memory");
        } else {
            unsigned cur;
            do {
                __nanosleep(64);
                asm volatile("ld.global.relaxed.gpu.u32 %0, [%1];"
                             : "=r"(cur) : "l"(&g_bar_gen));
            } while (cur == gen);
            asm volatile("fence.acq_rel.gpu;" ::: "memory");
        }
    }
    __syncthreads();
}

// rec smem layout (bytes)
#define SMEM_BIAS 0
#define SMEM_W    1024                   // W hi: [1024k][24n] bf16, 48B rows = 48 KB
#define SMEM_WLO  (1024 + 49152)         // 50176
#define SMEM_ACT  (50176 + 49152)        // 99328: 4 bufs x 32 KB block-shared chunks
#define ABUF      32768                  // [2 planes][128 rows][128 B (64 k)], SW128
#define SMEM_TOT  (99328 + 4 * ABUF)     // 230,400 B
// red buffer (48 KB) aliases SMEM_ACT after the k-loop.

// ============================================================================
// GRU recurrence on mma.sync. Block-shared k64 chunk staging (coalesced),
// ring 4, distance 2, SINGLE sync per chunk:
//   { ldsm B(i); stage(i+2); commit; wait 2; __syncthreads(); compute(i) }
// Safe: a warp staging buf((i+2)&3)=buf((i-2)&3) has passed sync(i-1), which
// orders it after all warps' compute(i-2) -- the last consumer of that buffer.
// Warp (p=w&3, q=w>>2): m [32p,32p+32) x n24, k-sub-slice q*16 of each chunk.
// ============================================================================
__global__ void __launch_bounds__(RTHR, 1)
gru_rec_mma(const float* __restrict__ w_hh, const float* __restrict__ b_ih,
            const float* __restrict__ b_hh)
{
    extern __shared__ char smem[];
    const int tid  = threadIdx.x;
    const int wid  = tid >> 5;
    const int lane = tid & 31;
    const int bid  = blockIdx.x;
    const int j0   = bid * 8;
    const int p    = wid & 3;
    const int q    = wid >> 2;
    const uint32_t sb = (uint32_t)__cvta_generic_to_shared(smem);

    // persistent W hi/lo: [k][n=gate*8+u], 48B rows (conflict-free for ldsm2t)
    for (int idx = tid; idx < 24 * HID; idx += RTHR) {
        int n = idx >> 10, k = idx & 1023;
        float w = w_hh[((size_t)(n >> 3) * HID + j0 + (n & 7)) * HID + k];
        __nv_bfloat16 hi = __float2bfloat16(w);
        __nv_bfloat16 lo = __float2bfloat16(w - __bfloat162float(hi));
        uint32_t a = (uint32_t)(k * 48 + n * 2);
        *(__nv_bfloat16*)(smem + SMEM_W   + a) = hi;
        *(__nv_bfloat16*)(smem + SMEM_WLO + a) = lo;
    }
    if (tid < 8) {
        float* sB = (float*)(smem + SMEM_BIAS);
        int j = j0 + tid;
        sB[tid]      = b_ih[j] + b_hh[j];
        sB[8 + tid]  = b_ih[HID + j] + b_hh[HID + j];
        sB[16 + tid] = b_ih[2 * HID + j];
        sB[24 + tid] = b_hh[2 * HID + j];
    }
    for (int idx = bid * RTHR + tid; idx < BATCH * HID; idx += NBLK * RTHR)
        g_hzero[idx] = __float2bfloat16(0.0f);
    __syncthreads();
    grid_bar();

    // lane-constant maps
    const int relrow = ((lane >> 3) & 1) * 8 + (lane & 7);
    const int segA   = lane >> 4;
    const uint32_t offA0 = SW128((uint32_t)((32 * p + relrow) * 128 + q * 32 + segA * 16));
    const uint32_t offA1 = SW128((uint32_t)((32 * p + 16 + relrow) * 128 + q * 32 + segA * 16));
    const int rbB = lane & 15;
    // coalesced staging map: 8 lanes cover one 128B row segment
    const int spl   = tid >> 8;          // plane: 0 = hi, 1 = lo
    const int sidx  = tid & 255;
    const int srow0 = sidx >> 3;         // rows srow0 + i*32, i = 0..3
    const int scol  = (sidx & 7) * 16;   // byte col within 128B
    const int selm  = (sidx & 7) * 8;    // bf16 elems
    const int eu = tid & 7;
    const int em = tid >> 3;

    for (int t = 0; t < T_STEPS; ++t) {
        const __nv_bfloat16* hi_src = t ? g_h1hi + (size_t)(t - 1) * BATCH * HID : g_hzero;
        const __nv_bfloat16* lo_src = t ? g_h1lo + (size_t)(t - 1) * BATCH * HID : g_hzero;
        const __nv_bfloat16* splane = spl ? lo_src : hi_src;

        // prologue: stage chunks 0,1 into bufs 0,1
        #pragma unroll
        for (int pre = 0; pre < 2; ++pre) {
            uint32_t bb = sb + SMEM_ACT + (uint32_t)(pre * ABUF + spl * 16384);
            #pragma unroll
            for (int s = 0; s < 4; ++s) {
                int row = srow0 + s * 32;
                cp16(bb + SW128((uint32_t)(row * 128 + scol)),
                     splane + (size_t)row * HID + pre * 64 + selm);
            }
            asm volatile("cp.async.commit_group;");
        }

        // epilogue operand prefetch
        float gir[2], giz[2], gin[2], hpv[2];
        #pragma unroll
        for (int it = 0; it < 2; ++it) {
            int m = em + it * 64;
            const float* gp = g_gi + ((size_t)t * BATCH + m) * GATES + j0 + eu;
            gir[it] = ldcg_f32(gp);
            giz[it] = ldcg_f32(gp + HID);
            gin[it] = ldcg_f32(gp + 2 * HID);
            hpv[it] = t ? ldcg_f32(g_h1 + ((size_t)(t - 1) * BATCH + m) * HID + j0 + eu)
                        : 0.0f;
        }

        float c[2][3][4];
        #pragma unroll
        for (int mt = 0; mt < 2; ++mt)
            #pragma unroll
            for (int g = 0; g < 3; ++g)
                #pragma unroll
                for (int x = 0; x < 4; ++x) c[mt][g][x] = 0.0f;

        #pragma unroll 1
        for (int i = 0; i < 16; ++i) {
            // B fragments for chunk i (persistent W -- hazard-free, hides
            // ldsm latency under the cp.async drain below)
            const int kb = i * 64 + q * 16;
            uint32_t bh[3][2], bl[3][2];
            #pragma unroll
            for (int g = 0; g < 3; ++g) {
                uint32_t a = (uint32_t)((kb + rbB) * 48 + g * 16);
                ldsm2t(bh[g], sb + SMEM_W + a);
                ldsm2t(bl[g], sb + SMEM_WLO + a);
            }

            if (i + 2 < 16) {
                uint32_t bb = sb + SMEM_ACT + (uint32_t)(((i + 2) & 3) * ABUF + spl * 16384);
                #pragma unroll
                for (int s = 0; s < 4; ++s) {
                    int row = srow0 + s * 32;
                    cp16(bb + SW128((uint32_t)(row * 128 + scol)),
                         splane + (size_t)row * HID + (i + 2) * 64 + selm);
                }
                asm volatile("cp.async.commit_group;");
                asm volatile("cp.async.wait_group 2;");
            } else {
                asm volatile("cp.async.wait_group 0;");
            }
            __syncthreads();   // single barrier: publishes chunk i, guards reuse

            const uint32_t abase = sb + SMEM_ACT + (uint32_t)((i & 3) * ABUF);
            #pragma unroll
            for (int mt = 0; mt < 2; ++mt) {
                uint32_t off = mt ? offA1 : offA0;
                uint32_t ah[4], al[4];
                ldsm4(ah, abase + off);
                ldsm4(al, abase + 16384 + off);
                #pragma unroll
                for (int g = 0; g < 3; ++g) {
                    mma16816(c[mt][g], ah, bh[g]);
                    mma16816(c[mt][g], al, bh[g]);
                    mma16816(c[mt][g], ah, bl[g]);
                }
            }
        }

        __syncthreads();   // act bufs idle; red aliases them
        float* red = (float*)(smem + SMEM_ACT);   // [128 m][24 n][4 q]
        {
            const int rr0 = p * 32 + (lane >> 2);
            const int c2  = (lane & 3) * 2;
            #pragma unroll
            for (int mt = 0; mt < 2; ++mt) {
                int rr = rr0 + mt * 16;
                #pragma unroll
                for (int g = 0; g < 3; ++g) {
                    int nn = g * 8 + c2;
                    red[(rr * 24 + nn) * 4 + q]           = c[mt][g][0];
                    red[(rr * 24 + nn + 1) * 4 + q]       = c[mt][g][1];
                    red[((rr + 8) * 24 + nn) * 4 + q]     = c[mt][g][2];
                    red[((rr + 8) * 24 + nn + 1) * 4 + q] = c[mt][g][3];
                }
            }
        }
        __syncthreads();

        {
            const float* sB = (const float*)(smem + SMEM_BIAS);
            #pragma unroll
            for (int it = 0; it < 2; ++it) {
                int m = em + it * 64;
                float4 vr = *(const float4*)(red + ((size_t)m * 24 + eu) * 4);
                float4 vz = *(const float4*)(red + ((size_t)m * 24 + 8 + eu) * 4);
                float4 vn = *(const float4*)(red + ((size_t)m * 24 + 16 + eu) * 4);
                float ghr = (vr.x + vr.y) + (vr.z + vr.w);
                float ghz = (vz.x + vz.y) + (vz.z + vz.w);
                float ghn = (vn.x + vn.y) + (vn.z + vn.w);
                float rg = 1.0f / (1.0f + expf(-(gir[it] + ghr + sB[eu])));
                float zg = 1.0f / (1.0f + expf(-(giz[it] + ghz + sB[8 + eu])));
                float ng = tanhf(gin[it] + sB[16 + eu] + rg * (ghn + sB[24 + eu]));
                float h  = (1.0f - zg) * ng + zg * hpv[it];

                __nv_bfloat16 hi = __float2bfloat16(h);
                __nv_bfloat16 lo = __float2bfloat16(h - __bfloat162float(hi));
                size_t o = ((size_t)t * BATCH + m) * HID + j0 + eu;
                g_h1hi[o] = hi;
                g_h1lo[o] = lo;
                g_h1[o]   = h;
            }
        }

        grid_bar();
    }
}

// ============================================================================
// Transpose + bf16-split w_ih1: [3072 n][1024 k] fp32 -> [k][n] hi/lo planes.
// ============================================================================
__global__ void __launch_bounds__(256)
conv_w(const float* __restrict__ w)
{
    __shared__ float tile[32][33];
    const int tx = threadIdx.x & 31;
    const int ty = threadIdx.x >> 5;
    const int k0 = blockIdx.x * 32;
    const int n0 = blockIdx.y * 32;
    #pragma unroll
    for (int r = 0; r < 4; ++r)
        tile[ty + r * 8][tx] = w[(size_t)(n0 + ty + r * 8) * HID + k0 + tx];
    __syncthreads();
    #pragma unroll
    for (int r = 0; r < 4; ++r) {
        float v = tile[tx][ty + r * 8];
        __nv_bfloat16 hi = __float2bfloat16(v);
        __nv_bfloat16 lo = __float2bfloat16(v - __bfloat162float(hi));
        size_t o = (size_t)(k0 + ty + r * 8) * GATES + n0 + tx;
        g_wbhi[o] = hi;
        g_wblo[o] = lo;
    }
}

// ============================================================================
// gi1 = h1 @ w_ih1^T on mma.sync (bf16 3-split). Tile 128m x 128n, K=1024.
// (unchanged from R11)
// ============================================================================
#define GST 16384
__global__ void __launch_bounds__(512)
gemm_bf16_3s(float* __restrict__ C)
{
    extern __shared__ char gsm[];   // 4 * 16384
    const int tid  = threadIdx.x;
    const int wid  = tid >> 5;
    const int lane = tid & 31;
    const int m0 = blockIdx.y * 128;
    const int n0 = blockIdx.x * 128;
    const int p  = wid & 3;
    const int nq = wid >> 2;
    const uint32_t sb = (uint32_t)__cvta_generic_to_shared(gsm);

    const int relrow = ((lane >> 3) & 1) * 8 + (lane & 7);
    const int segA   = lane >> 4;
    const uint32_t offA0 = SWA((uint32_t)((p * 32 + relrow) * 32 + segA * 16));
    const uint32_t offA1 = SWA((uint32_t)((p * 32 + 16 + relrow) * 32 + segA * 16));
    const int rbB = lane & 15;
    uint32_t offB[4];
    #pragma unroll
    for (int nt = 0; nt < 4; ++nt)
        offB[nt] = (uint32_t)(8192 + rbB * 256) + SWR(rbB, (uint32_t)(nq * 64 + nt * 16));

    // staging maps
    const bool stA = (tid < 256);
    const int  apl = (tid >> 7) & 1;
    const int  am  = tid & 127;
    const int  bix = tid & 255;
    const int  bpl = bix >> 7;
    const int  brw = (bix & 127) >> 3;
    const int  bcs = (bix & 7) * 32;

    const __nv_bfloat16* Asrc = (apl ? g_h1lo : g_h1hi) + (size_t)(m0 + am) * HID;
    const __nv_bfloat16* Bpl  = (bpl ? g_wblo : g_wbhi) + n0 + bcs / 2;
    const uint32_t adst0 = (uint32_t)(apl * 4096) + SWA((uint32_t)(am * 32));
    const uint32_t adst1 = (uint32_t)(apl * 4096) + SWA((uint32_t)(am * 32 + 16));
    const uint32_t bdst0 = (uint32_t)(8192 + bpl * 4096 + brw * 256)
                         + SWR(brw, (uint32_t)bcs);
    const uint32_t bdst1 = (uint32_t)(8192 + bpl * 4096 + brw * 256)
                         + SWR(brw, (uint32_t)(bcs + 16));

    float c[2][4][4];
    #pragma unroll
    for (int mt = 0; mt < 2; ++mt)
        #pragma unroll
        for (int nt = 0; nt < 4; ++nt)
            #pragma unroll
            for (int x = 0; x < 4; ++x) c[mt][nt][x] = 0.0f;

    #pragma unroll
    for (int pre = 0; pre < 3; ++pre) {
        uint32_t base = sb + (uint32_t)(pre * GST);
        if (stA) {
            cp16(base + adst0, Asrc + pre * 16);
            cp16(base + adst1, Asrc + pre * 16 + 8);
        } else {
            const __nv_bfloat16* s = Bpl + (size_t)(pre * 16 + brw) * GATES;
            cp16(base + bdst0, s);
            cp16(base + bdst1, s + 8);
        }
        asm volatile("cp.async.commit_group;");
    }

    #pragma unroll 1
    for (int i = 0; i < 64; ++i) {
        __syncthreads();
        if (i + 3 < 64) {
            uint32_t base = sb + (uint32_t)(((i + 3) & 3) * GST);
            if (stA) {
                cp16(base + adst0, Asrc + (i + 3) * 16);
                cp16(base + adst1, Asrc + (i + 3) * 16 + 8);
            } else {
                const __nv_bfloat16* s = Bpl + (size_t)((i + 3) * 16 + brw) * GATES;
                cp16(base + bdst0, s);
                cp16(base + bdst1, s + 8);
            }
            asm volatile("cp.async.commit_group;");
            asm volatile("cp.async.wait_group 3;");
        } else {
            asm volatile("cp.async.wait_group 0;");
        }
        __syncthreads();

        const uint32_t base = sb + (uint32_t)((i & 3) * GST);
        uint32_t bh[4][2], bl[4][2];
        #pragma unroll
        for (int nt = 0; nt < 4; ++nt) {
            ldsm2t(bh[nt], base + offB[nt]);
            ldsm2t(bl[nt], base + offB[nt] + 4096);
        }
        #pragma unroll
        for (int mt = 0; mt < 2; ++mt) {
            uint32_t off = mt ? offA1 : offA0;
            uint32_t ah[4], al[4];
            ldsm4(ah, base + off);
            ldsm4(al, base + 4096 + off);
            #pragma unroll
            for (int nt = 0; nt < 4; ++nt) {
                mma16816(c[mt][nt], ah, bh[nt]);
                mma16816(c[mt][nt], al, bh[nt]);
                mma16816(c[mt][nt], ah, bl[nt]);
            }
        }
    }

    #pragma unroll
    for (int mt = 0; mt < 2; ++mt) {
        int row = m0 + p * 32 + mt * 16 + (lane >> 2);
        #pragma unroll
        for (int nt = 0; nt < 4; ++nt) {
            int col = n0 + nq * 32 + nt * 8 + (lane & 3) * 2;
            *(float2*)(C + (size_t)row * GATES + col) =
                make_float2(c[mt][nt][0], c[mt][nt][1]);
            *(float2*)(C + (size_t)(row + 8) * GATES + col) =
                make_float2(c[mt][nt][2], c[mt][nt][3]);
        }
    }
}

// ============================================================================
// gi0 = x @ w_ih0^T  (K=64, fp32 f32x2)
// ============================================================================
#define GKC 16
__global__ void __launch_bounds__(256)
gemm_tn_f32x2(const float* __restrict__ A, const float* __restrict__ B,
              float* __restrict__ C, int M, int N, int K)
{
    __shared__ float sA[GKC][132];
    __shared__ float sB[GKC][132];
    const int tid = threadIdx.x;
    const int m0  = blockIdx.y * 128;
    const int n0  = blockIdx.x * 128;
    const int ty  = tid >> 4, tx = tid & 15;
    const int sr = tid >> 1;
    const int sk = (tid & 1) * 8;

    u64 acc[4][8];
    #pragma unroll
    for (int p = 0; p < 4; ++p)
        #pragma unroll
        for (int c = 0; c < 8; ++c) acc[p][c] = 0ull;

    const float* Ag = A + (size_t)(m0 + sr) * K + sk;
    const float* Bg = B + (size_t)(n0 + sr) * K + sk;
    float4 a0 = ldcg_f32x4(Ag);
    float4 a1 = ldcg_f32x4(Ag + 4);
    float4 b0 = ldcg_f32x4(Bg);
    float4 b1 = ldcg_f32x4(Bg + 4);

    for (int kc = 0; kc < K; kc += GKC) {
        sA[sk + 0][sr] = a0.x; sA[sk + 1][sr] = a0.y;
        sA[sk + 2][sr] = a0.z; sA[sk + 3][sr] = a0.w;
        sA[sk + 4][sr] = a1.x; sA[sk + 5][sr] = a1.y;
        sA[sk + 6][sr] = a1.z; sA[sk + 7][sr] = a1.w;
        sB[sk + 0][sr] = b0.x; sB[sk + 1][sr] = b0.y;
        sB[sk + 2][sr] = b0.z; sB[sk + 3][sr] = b0.w;
        sB[sk + 4][sr] = b1.x; sB[sk + 5][sr] = b1.y;
        sB[sk + 6][sr] = b1.z; sB[sk + 7][sr] = b1.w;
        if (kc + GKC < K) {
            Ag += GKC; Bg += GKC;
            a0 = ldcg_f32x4(Ag);
            a1 = ldcg_f32x4(Ag + 4);
            b0 = ldcg_f32x4(Bg);
            b1 = ldcg_f32x4(Bg + 4);
        }
        __syncthreads();
        #pragma unroll
        for (int kk = 0; kk < GKC; ++kk) {
            ulonglong2 aa = *(const ulonglong2*)(&sA[kk][ty * 8]);
            ulonglong2 ab = *(const ulonglong2*)(&sA[kk][ty * 8 + 4]);
            float4 bv0 = *(const float4*)(&sB[kk][tx * 8]);
            float4 bv1 = *(const float4*)(&sB[kk][tx * 8 + 4]);
            float bs[8] = {bv0.x, bv0.y, bv0.z, bv0.w, bv1.x, bv1.y, bv1.z, bv1.w};
            #pragma unroll
            for (int c = 0; c < 8; ++c) {
                u64 bd = dup2(bs[c]);
                fma2(acc[0][c], aa.x, bd);
                fma2(acc[1][c], aa.y, bd);
                fma2(acc[2][c], ab.x, bd);
                fma2(acc[3][c], ab.y, bd);
            }
        }
        __syncthreads();
    }

    #pragma unroll
    for (int p = 0; p < 4; ++p) {
        float2 v[8];
        #pragma unroll
        for (int c = 0; c < 8; ++c) v[c] = unpk(acc[p][c]);
        int row0 = m0 + ty * 8 + p * 2;
        float* c0 = C + (size_t)row0 * N + n0 + tx * 8;
        float* c1 = c0 + N;
        *(float4*)(c0)     = make_float4(v[0].x, v[1].x, v[2].x, v[3].x);
        *(float4*)(c0 + 4) = make_float4(v[4].x, v[5].x, v[6].x, v[7].x);
        *(float4*)(c1)     = make_float4(v[0].y, v[1].y, v[2].y, v[3].y);
        *(float4*)(c1 + 4) = make_float4(v[4].y, v[5].y, v[6].y, v[7].y);
    }
}

// ============================================================================
// out[t,b,o] = h2[t,b,:] . w_lin[o,:] + b_lin[o]  (h2 in g_h1)
// ============================================================================
__global__ void __launch_bounds__(256)
out_linear(const float* __restrict__ w_lin, const float* __restrict__ b_lin,
           float* __restrict__ out)
{
    __shared__ float sA[16][68];
    __shared__ float sB[16][68];
    const int tid = threadIdx.x;
    const size_t rb = (size_t)blockIdx.x * 64;
    const int ty = tid >> 4;
    const int tx = tid & 15;
    const int li   = tid * 4;
    const int srow = li >> 4;
    const int skk  = li & 15;

    float acc[4][4] = {};

    for (int kc = 0; kc < HID; kc += 16) {
        __syncthreads();
        float4 va = ldcg_f32x4(g_h1 + (rb + srow) * HID + kc + skk);
        sA[skk + 0][srow] = va.x; sA[skk + 1][srow] = va.y;
        sA[skk + 2][srow] = va.z; sA[skk + 3][srow] = va.w;
        float4 vb = *(const float4*)(w_lin + (size_t)srow * HID + kc + skk);
        sB[skk + 0][srow] = vb.x; sB[skk + 1][srow] = vb.y;
        sB[skk + 2][srow] = vb.z; sB[skk + 3][srow] = vb.w;
        __syncthreads();
        #pragma unroll
        for (int kk = 0; kk < 16; ++kk) {
            float4 a = *(const float4*)&sA[kk][ty * 4];
            float4 b = *(const float4*)&sB[kk][tx * 4];
            acc[0][0] = fmaf(a.x, b.x, acc[0][0]); acc[0][1] = fmaf(a.x, b.y, acc[0][1]);
            acc[0][2] = fmaf(a.x, b.z, acc[0][2]); acc[0][3] = fmaf(a.x, b.w, acc[0][3]);
            acc[1][0] = fmaf(a.y, b.x, acc[1][0]); acc[1][1] = fmaf(a.y, b.y, acc[1][1]);
            acc[1][2] = fmaf(a.y, b.z, acc[1][2]); acc[1][3] = fmaf(a.y, b.w, acc[1][3]);
            acc[2][0] = fmaf(a.z, b.x, acc[2][0]); acc[2][1] = fmaf(a.z, b.y, acc[2][1]);
            acc[2][2] = fmaf(a.z, b.z, acc[2][2]); acc[2][3] = fmaf(a.z, b.w, acc[2][3]);
            acc[3][0] = fmaf(a.w, b.x, acc[3][0]); acc[3][1] = fmaf(a.w, b.y, acc[3][1]);
            acc[3][2] = fmaf(a.w, b.z, acc[3][2]); acc[3][3] = fmaf(a.w, b.w, acc[3][3]);
        }
    }

    #pragma unroll
    for (int i = 0; i < 4; ++i) {
        float4 o4;
        o4.x = acc[i][0] + b_lin[tx * 4 + 0];
        o4.y = acc[i][1] + b_lin[tx * 4 + 1];
        o4.z = acc[i][2] + b_lin[tx * 4 + 2];
        o4.w = acc[i][3] + b_lin[tx * 4 + 3];
        *(float4*)(out + (rb + ty * 4 + i) * OUT_DIM + tx * 4) = o4;
    }
}

extern "C" void kernel_launch(void* const* d_in, const int* in_sizes, int n_in,
                              void* d_out, int out_size)
{
    const float* x     = (const float*)d_in[0];
    const float* w_ih0 = (const float*)d_in[1];
    const float* w_hh0 = (const float*)d_in[2];
    const float* b_ih0 = (const float*)d_in[3];
    const float* b_hh0 = (const float*)d_in[4];
    const float* w_ih1 = (const float*)d_in[5];
    const float* w_hh1 = (const float*)d_in[6];
    const float* b_ih1 = (const float*)d_in[7];
    const float* b_hh1 = (const float*)d_in[8];
    const float* w_lin = (const float*)d_in[9];
    const float* b_lin = (const float*)d_in[10];
    float* out = (float*)d_out;
    (void)in_sizes; (void)n_in; (void)out_size;

    float *gi_ptr;
    cudaGetSymbolAddress((void**)&gi_ptr, g_gi);

    cudaFuncSetAttribute(gru_rec_mma, cudaFuncAttributeMaxDynamicSharedMemorySize, SMEM_TOT);
    cudaFuncSetAttribute(gemm_bf16_3s, cudaFuncAttributeMaxDynamicSharedMemorySize, 4 * GST);

    // w_ih1 transpose + split (independent of layer 0)
    conv_w<<<dim3(HID / 32, GATES / 32), 256>>>(w_ih1);

    // layer 0
    gemm_tn_f32x2<<<dim3(GATES / 128, MROWS / 128), 256>>>(x, w_ih0, gi_ptr,
                                                           MROWS, GATES, IN_DIM);
    gru_rec_mma<<<NBLK, RTHR, SMEM_TOT>>>(w_hh0, b_ih0, b_hh0);

    // layer 1
    gemm_bf16_3s<<<dim3(GATES / 128, MROWS / 128), 512, 4 * GST>>>(gi_ptr);
    gru_rec_mma<<<NBLK, RTHR, SMEM_TOT>>>(w_hh1, b_ih1, b_hh1);

    // time-distributed linear
    out_linear<<<MROWS / 64, 256>>>(w_lin, b_lin, out);
}

// round 15
// speedup vs baseline: 1.2773x; 1.0425x over previous
#include <cuda_runtime.h>
#include <cuda_bf16.h>
#include <math.h>
#include <stdint.h>

#define T_STEPS 512
#define BATCH   128
#define IN_DIM  64
#define HID     1024
#define OUT_DIM 64
#define GATES   (3 * HID)
#define MROWS   (T_STEPS * BATCH)   // 65536
#define NBLK    128
#define RTHR    512

typedef unsigned long long u64;

// Persistent scratch (device globals -- no allocation anywhere).
__device__ float g_gi[(size_t)MROWS * GATES];        // input-side gates
__device__ float g_h1[(size_t)MROWS * HID];          // layer outputs (fp32)
__device__ __nv_bfloat16 g_h1hi[(size_t)MROWS * HID];// layer outputs, bf16 hi plane
__device__ __nv_bfloat16 g_h1lo[(size_t)MROWS * HID];// layer outputs, bf16 lo plane
__device__ __nv_bfloat16 g_hzero[BATCH * HID];       // zeros (h_{-1})
__device__ __nv_bfloat16 g_wbhi[(size_t)HID * GATES];// w_ih1 transposed [k][n], hi
__device__ __nv_bfloat16 g_wblo[(size_t)HID * GATES];// lo
__device__ unsigned g_bar_gen;
__device__ unsigned g_bar_cnt;

// ---------- helpers ----------
__device__ __forceinline__ void fma2(u64 &d, u64 a, u64 b) {
    asm("fma.rn.f32x2 %0, %1, %2, %0;" : "+l"(d) : "l"(a), "l"(b));
}
__device__ __forceinline__ u64 dup2(float x) {
    u64 r; asm("mov.b64 %0, {%1, %1};" : "=l"(r) : "f"(x)); return r;
}
__device__ __forceinline__ float2 unpk(u64 v) {
    float2 r; asm("mov.b64 {%0, %1}, %2;" : "=f"(r.x), "=f"(r.y) : "l"(v)); return r;
}
__device__ __forceinline__ float4 ldcg_f32x4(const void* p) {
    float4 v;
    asm volatile("ld.global.cg.v4.f32 {%0, %1, %2, %3}, [%4];"
                 : "=f"(v.x), "=f"(v.y), "=f"(v.z), "=f"(v.w) : "l"(p));
    return v;
}
__device__ __forceinline__ float ldcg_f32(const void* p) {
    float v;
    asm volatile("ld.global.cg.f32 %0, [%1];" : "=f"(v) : "l"(p));
    return v;
}
__device__ __forceinline__ void cp16(unsigned d, const void* s) {
    asm volatile("cp.async.cg.shared.global [%0], [%1], 16;" :: "r"(d), "l"(s));
}
__device__ __forceinline__ void ldsm4(uint32_t* r, uint32_t a) {
    asm volatile("ldmatrix.sync.aligned.m8n8.x4.shared.b16 {%0,%1,%2,%3}, [%4];"
                 : "=r"(r[0]), "=r"(r[1]), "=r"(r[2]), "=r"(r[3]) : "r"(a));
}
__device__ __forceinline__ void ldsm2t(uint32_t* r, uint32_t a) {
    asm volatile("ldmatrix.sync.aligned.m8n8.x2.trans.shared.b16 {%0,%1}, [%2];"
                 : "=r"(r[0]), "=r"(r[1]) : "r"(a));
}
__device__ __forceinline__ void mma16816(float* c, const uint32_t* a, const uint32_t* b) {
    asm volatile("mma.sync.aligned.m16n8k16.row.col.f32.bf16.bf16.f32 "
                 "{%0,%1,%2,%3}, {%4,%5,%6,%7}, {%8,%9}, {%0,%1,%2,%3};"
                 : "+f"(c[0]), "+f"(c[1]), "+f"(c[2]), "+f"(c[3])
                 : "r"(a[0]), "r"(a[1]), "r"(a[2]), "r"(a[3]), "r"(b[0]), "r"(b[1]));
}
// swizzles (byte-offset XOR)
__device__ __forceinline__ uint32_t SWA(uint32_t a) { return a ^ ((a >> 3) & 0x10); }   // 32B rows
__device__ __forceinline__ uint32_t SW128(uint32_t a){ return a ^ ((a >> 3) & 0x70); }  // 128B rows
__device__ __forceinline__ uint32_t SWR(int row, uint32_t c) { return c ^ (((uint32_t)row & 7u) << 4); }

// ---- grid barrier: release/acquire, nanosleep poll ----
__device__ __forceinline__ void grid_bar() {
    __syncthreads();
    if (threadIdx.x == 0) {
        unsigned gen;
        asm volatile("ld.global.relaxed.gpu.u32 %0, [%1];"
                     : "=r"(gen) : "l"(&g_bar_gen));
        asm volatile("fence.acq_rel.gpu;" ::: "memory");
        unsigned prev = atomicAdd(&g_bar_cnt, 1u);
        if (prev == (unsigned)(NBLK - 1)) {
            asm volatile("st.global.relaxed.gpu.u32 [%0], %1;"
                         :: "l"(&g_bar_cnt), "r"(0u) : "memory");
            asm volatile("fence.acq_rel.gpu;" ::: "memory");
            asm volatile("st.global.relaxed.gpu.u32 [%0], %1;"
                         :: "l"(&g_bar_gen), "r"(gen + 1u) : "memory");
        } else {
            unsigned cur;
            do {
                __nanosleep(64);
                asm volatile("ld.global.relaxed.gpu.u32 %0, [%1];"
                             : "=r"(cur) : "l"(&g_bar_gen));
            } while (cur == gen);
            asm volatile("fence.acq_rel.gpu;" ::: "memory");
        }
    }
    __syncthreads();
}

// rec smem layout (bytes)
#define SMEM_BIAS 0
#define SMEM_W    1024                   // W hi: [1024k][24n] bf16, 48B rows = 48 KB
#define SMEM_WLO  (1024 + 49152)         // 50176
#define SMEM_ACT  (50176 + 49152)        // 99328: 4 bufs x 32 KB block-shared chunks
#define ABUF      32768                  // [2 planes][128 rows][128 B (64 k)], SW128
#define SMEM_TOT  (99328 + 4 * ABUF)     // 230,400 B
// red buffer (48 KB) aliases SMEM_ACT after the k-loop.

// ============================================================================
// GRU recurrence on mma.sync (unchanged from R14: single sync per chunk,
// ring 4, distance 2, hoisted B fragments).
// ============================================================================
__global__ void __launch_bounds__(RTHR, 1)
gru_rec_mma(const float* __restrict__ w_hh, const float* __restrict__ b_ih,
            const float* __restrict__ b_hh)
{
    extern __shared__ char smem[];
    const int tid  = threadIdx.x;
    const int wid  = tid >> 5;
    const int lane = tid & 31;
    const int bid  = blockIdx.x;
    const int j0   = bid * 8;
    const int p    = wid & 3;
    const int q    = wid >> 2;
    const uint32_t sb = (uint32_t)__cvta_generic_to_shared(smem);

    for (int idx = tid; idx < 24 * HID; idx += RTHR) {
        int n = idx >> 10, k = idx & 1023;
        float w = w_hh[((size_t)(n >> 3) * HID + j0 + (n & 7)) * HID + k];
        __nv_bfloat16 hi = __float2bfloat16(w);
        __nv_bfloat16 lo = __float2bfloat16(w - __bfloat162float(hi));
        uint32_t a = (uint32_t)(k * 48 + n * 2);
        *(__nv_bfloat16*)(smem + SMEM_W   + a) = hi;
        *(__nv_bfloat16*)(smem + SMEM_WLO + a) = lo;
    }
    if (tid < 8) {
        float* sB = (float*)(smem + SMEM_BIAS);
        int j = j0 + tid;
        sB[tid]      = b_ih[j] + b_hh[j];
        sB[8 + tid]  = b_ih[HID + j] + b_hh[HID + j];
        sB[16 + tid] = b_ih[2 * HID + j];
        sB[24 + tid] = b_hh[2 * HID + j];
    }
    for (int idx = bid * RTHR + tid; idx < BATCH * HID; idx += NBLK * RTHR)
        g_hzero[idx] = __float2bfloat16(0.0f);
    __syncthreads();
    grid_bar();

    const int relrow = ((lane >> 3) & 1) * 8 + (lane & 7);
    const int segA   = lane >> 4;
    const uint32_t offA0 = SW128((uint32_t)((32 * p + relrow) * 128 + q * 32 + segA * 16));
    const uint32_t offA1 = SW128((uint32_t)((32 * p + 16 + relrow) * 128 + q * 32 + segA * 16));
    const int rbB = lane & 15;
    const int spl   = tid >> 8;
    const int sidx  = tid & 255;
    const int srow0 = sidx >> 3;
    const int scol  = (sidx & 7) * 16;
    const int selm  = (sidx & 7) * 8;
    const int eu = tid & 7;
    const int em = tid >> 3;

    for (int t = 0; t < T_STEPS; ++t) {
        const __nv_bfloat16* hi_src = t ? g_h1hi + (size_t)(t - 1) * BATCH * HID : g_hzero;
        const __nv_bfloat16* lo_src = t ? g_h1lo + (size_t)(t - 1) * BATCH * HID : g_hzero;
        const __nv_bfloat16* splane = spl ? lo_src : hi_src;

        #pragma unroll
        for (int pre = 0; pre < 2; ++pre) {
            uint32_t bb = sb + SMEM_ACT + (uint32_t)(pre * ABUF + spl * 16384);
            #pragma unroll
            for (int s = 0; s < 4; ++s) {
                int row = srow0 + s * 32;
                cp16(bb + SW128((uint32_t)(row * 128 + scol)),
                     splane + (size_t)row * HID + pre * 64 + selm);
            }
            asm volatile("cp.async.commit_group;");
        }

        float gir[2], giz[2], gin[2], hpv[2];
        #pragma unroll
        for (int it = 0; it < 2; ++it) {
            int m = em + it * 64;
            const float* gp = g_gi + ((size_t)t * BATCH + m) * GATES + j0 + eu;
            gir[it] = ldcg_f32(gp);
            giz[it] = ldcg_f32(gp + HID);
            gin[it] = ldcg_f32(gp + 2 * HID);
            hpv[it] = t ? ldcg_f32(g_h1 + ((size_t)(t - 1) * BATCH + m) * HID + j0 + eu)
                        : 0.0f;
        }

        float c[2][3][4];
        #pragma unroll
        for (int mt = 0; mt < 2; ++mt)
            #pragma unroll
            for (int g = 0; g < 3; ++g)
                #pragma unroll
                for (int x = 0; x < 4; ++x) c[mt][g][x] = 0.0f;

        #pragma unroll 1
        for (int i = 0; i < 16; ++i) {
            const int kb = i * 64 + q * 16;
            uint32_t bh[3][2], bl[3][2];
            #pragma unroll
            for (int g = 0; g < 3; ++g) {
                uint32_t a = (uint32_t)((kb + rbB) * 48 + g * 16);
                ldsm2t(bh[g], sb + SMEM_W + a);
                ldsm2t(bl[g], sb + SMEM_WLO + a);
            }

            if (i + 2 < 16) {
                uint32_t bb = sb + SMEM_ACT + (uint32_t)(((i + 2) & 3) * ABUF + spl * 16384);
                #pragma unroll
                for (int s = 0; s < 4; ++s) {
                    int row = srow0 + s * 32;
                    cp16(bb + SW128((uint32_t)(row * 128 + scol)),
                         splane + (size_t)row * HID + (i + 2) * 64 + selm);
                }
                asm volatile("cp.async.commit_group;");
                asm volatile("cp.async.wait_group 2;");
            } else {
                asm volatile("cp.async.wait_group 0;");
            }
            __syncthreads();

            const uint32_t abase = sb + SMEM_ACT + (uint32_t)((i & 3) * ABUF);
            #pragma unroll
            for (int mt = 0; mt < 2; ++mt) {
                uint32_t off = mt ? offA1 : offA0;
                uint32_t ah[4], al[4];
                ldsm4(ah, abase + off);
                ldsm4(al, abase + 16384 + off);
                #pragma unroll
                for (int g = 0; g < 3; ++g) {
                    mma16816(c[mt][g], ah, bh[g]);
                    mma16816(c[mt][g], al, bh[g]);
                    mma16816(c[mt][g], ah, bl[g]);
                }
            }
        }

        __syncthreads();
        float* red = (float*)(smem + SMEM_ACT);   // [128 m][24 n][4 q]
        {
            const int rr0 = p * 32 + (lane >> 2);
            const int c2  = (lane & 3) * 2;
            #pragma unroll
            for (int mt = 0; mt < 2; ++mt) {
                int rr = rr0 + mt * 16;
                #pragma unroll
                for (int g = 0; g < 3; ++g) {
                    int nn = g * 8 + c2;
                    red[(rr * 24 + nn) * 4 + q]           = c[mt][g][0];
                    red[(rr * 24 + nn + 1) * 4 + q]       = c[mt][g][1];
                    red[((rr + 8) * 24 + nn) * 4 + q]     = c[mt][g][2];
                    red[((rr + 8) * 24 + nn + 1) * 4 + q] = c[mt][g][3];
                }
            }
        }
        __syncthreads();

        {
            const float* sB = (const float*)(smem + SMEM_BIAS);
            #pragma unroll
            for (int it = 0; it < 2; ++it) {
                int m = em + it * 64;
                float4 vr = *(const float4*)(red + ((size_t)m * 24 + eu) * 4);
                float4 vz = *(const float4*)(red + ((size_t)m * 24 + 8 + eu) * 4);
                float4 vn = *(const float4*)(red + ((size_t)m * 24 + 16 + eu) * 4);
                float ghr = (vr.x + vr.y) + (vr.z + vr.w);
                float ghz = (vz.x + vz.y) + (vz.z + vz.w);
                float ghn = (vn.x + vn.y) + (vn.z + vn.w);
                float rg = 1.0f / (1.0f + expf(-(gir[it] + ghr + sB[eu])));
                float zg = 1.0f / (1.0f + expf(-(giz[it] + ghz + sB[8 + eu])));
                float ng = tanhf(gin[it] + sB[16 + eu] + rg * (ghn + sB[24 + eu]));
                float h  = (1.0f - zg) * ng + zg * hpv[it];

                __nv_bfloat16 hi = __float2bfloat16(h);
                __nv_bfloat16 lo = __float2bfloat16(h - __bfloat162float(hi));
                size_t o = ((size_t)t * BATCH + m) * HID + j0 + eu;
                g_h1hi[o] = hi;
                g_h1lo[o] = lo;
                g_h1[o]   = h;
            }
        }

        grid_bar();
    }
}

// ============================================================================
// Transpose + bf16-split w_ih1: [3072 n][1024 k] fp32 -> [k][n] hi/lo planes.
// ============================================================================
__global__ void __launch_bounds__(256)
conv_w(const float* __restrict__ w)
{
    __shared__ float tile[32][33];
    const int tx = threadIdx.x & 31;
    const int ty = threadIdx.x >> 5;
    const int k0 = blockIdx.x * 32;
    const int n0 = blockIdx.y * 32;
    #pragma unroll
    for (int r = 0; r < 4; ++r)
        tile[ty + r * 8][tx] = w[(size_t)(n0 + ty + r * 8) * HID + k0 + tx];
    __syncthreads();
    #pragma unroll
    for (int r = 0; r < 4; ++r) {
        float v = tile[tx][ty + r * 8];
        __nv_bfloat16 hi = __float2bfloat16(v);
        __nv_bfloat16 lo = __float2bfloat16(v - __bfloat162float(hi));
        size_t o = (size_t)(k0 + ty + r * 8) * GATES + n0 + tx;
        g_wbhi[o] = hi;
        g_wblo[o] = lo;
    }
}

// ============================================================================
// gi1 = h1 @ w_ih1^T on mma.sync (bf16 3-split). Tile 128m x 256n, K=1024.
// Buffer = A[2pl][128m][32B] (8KB, SWA) + B[2pl][16k][512B] (16KB, SWR) = 24KB.
// Ring 4 (96 KB), distance 2, SINGLE sync per chunk (R14-proven pattern).
// Warp (p=wid&3: 32m, nq=wid>>2: 64n). Per-nt B frag load + immediate MMA.
// ============================================================================
#define GST 24576
__global__ void __launch_bounds__(512)
gemm_bf16_3s(float* __restrict__ C)
{
    extern __shared__ char gsm[];   // 4 * 24576
    const int tid  = threadIdx.x;
    const int wid  = tid >> 5;
    const int lane = tid & 31;
    const int m0 = blockIdx.y * 128;
    const int n0 = blockIdx.x * 256;
    const int p  = wid & 3;
    const int nq = wid >> 2;
    const uint32_t sb = (uint32_t)__cvta_generic_to_shared(gsm);

    const int relrow = ((lane >> 3) & 1) * 8 + (lane & 7);
    const int segA   = lane >> 4;
    const uint32_t offA0 = SWA((uint32_t)((p * 32 + relrow) * 32 + segA * 16));
    const uint32_t offA1 = SWA((uint32_t)((p * 32 + 16 + relrow) * 32 + segA * 16));
    const int rbB = lane & 15;
    uint32_t offB[8];
    #pragma unroll
    for (int nt = 0; nt < 8; ++nt)
        offB[nt] = (uint32_t)(8192 + rbB * 512) + SWR(rbB, (uint32_t)(nq * 128 + nt * 16));

    // staging maps: tid<256 -> A (2 planes x 128 rows x 32B, 2 cp16 each);
    // tid>=256 -> B (2 planes x 16 rows x 512B; 8 thr/row, 64B = 4 cp16 each)
    const bool stA = (tid < 256);
    const int  apl = (tid >> 7) & 1;
    const int  am  = tid & 127;
    const int  bix = tid & 255;
    const int  bpl = bix >> 7;
    const int  bsub = bix & 127;
    const int  brw  = bsub >> 3;          // k row 0..15
    const int  bcb  = (bsub & 7) * 64;    // byte col base within 512B

    const __nv_bfloat16* Asrc = (apl ? g_h1lo : g_h1hi) + (size_t)(m0 + am) * HID;
    const __nv_bfloat16* Bsrc = (bpl ? g_wblo : g_wbhi) + n0 + bcb / 2;   // + j*8 elems
    const uint32_t adst0 = (uint32_t)(apl * 4096) + SWA((uint32_t)(am * 32));
    const uint32_t adst1 = (uint32_t)(apl * 4096) + SWA((uint32_t)(am * 32 + 16));
    uint32_t bdst[4];
    #pragma unroll
    for (int jj = 0; jj < 4; ++jj)
        bdst[jj] = (uint32_t)(8192 + bpl * 8192 + brw * 512)
                 + SWR(brw, (uint32_t)(bcb + jj * 16));

    float c[2][8][4];
    #pragma unroll
    for (int mt = 0; mt < 2; ++mt)
        #pragma unroll
        for (int nt = 0; nt < 8; ++nt)
            #pragma unroll
            for (int x = 0; x < 4; ++x) c[mt][nt][x] = 0.0f;

    // prologue: stage chunks 0,1
    #pragma unroll
    for (int pre = 0; pre < 2; ++pre) {
        uint32_t base = sb + (uint32_t)(pre * GST);
        if (stA) {
            cp16(base + adst0, Asrc + pre * 16);
            cp16(base + adst1, Asrc + pre * 16 + 8);
        } else {
            const __nv_bfloat16* s = Bsrc + (size_t)(pre * 16 + brw) * GATES;
            #pragma unroll
            for (int jj = 0; jj < 4; ++jj)
                cp16(base + bdst[jj], s + jj * 8);
        }
        asm volatile("cp.async.commit_group;");
    }

    #pragma unroll 1
    for (int i = 0; i < 64; ++i) {
        if (i + 2 < 64) {
            uint32_t base = sb + (uint32_t)(((i + 2) & 3) * GST);
            if (stA) {
                cp16(base + adst0, Asrc + (i + 2) * 16);
                cp16(base + adst1, Asrc + (i + 2) * 16 + 8);
            } else {
                const __nv_bfloat16* s = Bsrc + (size_t)((i + 2) * 16 + brw) * GATES;
                #pragma unroll
                for (int jj = 0; jj < 4; ++jj)
                    cp16(base + bdst[jj], s + jj * 8);
            }
            asm volatile("cp.async.commit_group;");
            asm volatile("cp.async.wait_group 2;");
        } else {
            asm volatile("cp.async.wait_group 0;");
        }
        __syncthreads();   // single barrier: publishes chunk i, guards buffer reuse

        const uint32_t base = sb + (uint32_t)((i & 3) * GST);
        uint32_t ah[2][4], al[2][4];
        ldsm4(ah[0], base + offA0);
        ldsm4(ah[1], base + offA1);
        ldsm4(al[0], base + 4096 + offA0);
        ldsm4(al[1], base + 4096 + offA1);
        #pragma unroll
        for (int nt = 0; nt < 8; ++nt) {
            uint32_t bh[2], blv[2];
            ldsm2t(bh, base + offB[nt]);
            ldsm2t(blv, base + offB[nt] + 8192);
            #pragma unroll
            for (int mt = 0; mt < 2; ++mt) {
                mma16816(c[mt][nt], ah[mt], bh);
                mma16816(c[mt][nt], al[mt], bh);
                mma16816(c[mt][nt], ah[mt], blv);
            }
        }
    }

    #pragma unroll
    for (int mt = 0; mt < 2; ++mt) {
        int row = m0 + p * 32 + mt * 16 + (lane >> 2);
        #pragma unroll
        for (int nt = 0; nt < 8; ++nt) {
            int col = n0 + nq * 64 + nt * 8 + (lane & 3) * 2;
            *(float2*)(C + (size_t)row * GATES + col) =
                make_float2(c[mt][nt][0], c[mt][nt][1]);
            *(float2*)(C + (size_t)(row + 8) * GATES + col) =
                make_float2(c[mt][nt][2], c[mt][nt][3]);
        }
    }
}

// ============================================================================
// gi0 = x @ w_ih0^T  (K=64, fp32 f32x2)
// ============================================================================
#define GKC 16
__global__ void __launch_bounds__(256)
gemm_tn_f32x2(const float* __restrict__ A, const float* __restrict__ B,
              float* __restrict__ C, int M, int N, int K)
{
    __shared__ float sA[GKC][132];
    __shared__ float sB[GKC][132];
    const int tid = threadIdx.x;
    const int m0  = blockIdx.y * 128;
    const int n0  = blockIdx.x * 128;
    const int ty  = tid >> 4, tx = tid & 15;
    const int sr = tid >> 1;
    const int sk = (tid & 1) * 8;

    u64 acc[4][8];
    #pragma unroll
    for (int p = 0; p < 4; ++p)
        #pragma unroll
        for (int c = 0; c < 8; ++c) acc[p][c] = 0ull;

    const float* Ag = A + (size_t)(m0 + sr) * K + sk;
    const float* Bg = B + (size_t)(n0 + sr) * K + sk;
    float4 a0 = ldcg_f32x4(Ag);
    float4 a1 = ldcg_f32x4(Ag + 4);
    float4 b0 = ldcg_f32x4(Bg);
    float4 b1 = ldcg_f32x4(Bg + 4);

    for (int kc = 0; kc < K; kc += GKC) {
        sA[sk + 0][sr] = a0.x; sA[sk + 1][sr] = a0.y;
        sA[sk + 2][sr] = a0.z; sA[sk + 3][sr] = a0.w;
        sA[sk + 4][sr] = a1.x; sA[sk + 5][sr] = a1.y;
        sA[sk + 6][sr] = a1.z; sA[sk + 7][sr] = a1.w;
        sB[sk + 0][sr] = b0.x; sB[sk + 1][sr] = b0.y;
        sB[sk + 2][sr] = b0.z; sB[sk + 3][sr] = b0.w;
        sB[sk + 4][sr] = b1.x; sB[sk + 5][sr] = b1.y;
        sB[sk + 6][sr] = b1.z; sB[sk + 7][sr] = b1.w;
        if (kc + GKC < K) {
            Ag += GKC; Bg += GKC;
            a0 = ldcg_f32x4(Ag);
            a1 = ldcg_f32x4(Ag + 4);
            b0 = ldcg_f32x4(Bg);
            b1 = ldcg_f32x4(Bg + 4);
        }
        __syncthreads();
        #pragma unroll
        for (int kk = 0; kk < GKC; ++kk) {
            ulonglong2 aa = *(const ulonglong2*)(&sA[kk][ty * 8]);
            ulonglong2 ab = *(const ulonglong2*)(&sA[kk][ty * 8 + 4]);
            float4 bv0 = *(const float4*)(&sB[kk][tx * 8]);
            float4 bv1 = *(const float4*)(&sB[kk][tx * 8 + 4]);
            float bs[8] = {bv0.x, bv0.y, bv0.z, bv0.w, bv1.x, bv1.y, bv1.z, bv1.w};
            #pragma unroll
            for (int c = 0; c < 8; ++c) {
                u64 bd = dup2(bs[c]);
                fma2(acc[0][c], aa.x, bd);
                fma2(acc[1][c], aa.y, bd);
                fma2(acc[2][c], ab.x, bd);
                fma2(acc[3][c], ab.y, bd);
            }
        }
        __syncthreads();
    }

    #pragma unroll
    for (int p = 0; p < 4; ++p) {
        float2 v[8];
        #pragma unroll
        for (int c = 0; c < 8; ++c) v[c] = unpk(acc[p][c]);
        int row0 = m0 + ty * 8 + p * 2;
        float* c0 = C + (size_t)row0 * N + n0 + tx * 8;
        float* c1 = c0 + N;
        *(float4*)(c0)     = make_float4(v[0].x, v[1].x, v[2].x, v[3].x);
        *(float4*)(c0 + 4) = make_float4(v[4].x, v[5].x, v[6].x, v[7].x);
        *(float4*)(c1)     = make_float4(v[0].y, v[1].y, v[2].y, v[3].y);
        *(float4*)(c1 + 4) = make_float4(v[4].y, v[5].y, v[6].y, v[7].y);
    }
}

// ============================================================================
// out[t,b,o] = h2[t,b,:] . w_lin[o,:] + b_lin[o]  (h2 in g_h1)
// ============================================================================
__global__ void __launch_bounds__(256)
out_linear(const float* __restrict__ w_lin, const float* __restrict__ b_lin,
           float* __restrict__ out)
{
    __shared__ float sA[16][68];
    __shared__ float sB[16][68];
    const int tid = threadIdx.x;
    const size_t rb = (size_t)blockIdx.x * 64;
    const int ty = tid >> 4;
    const int tx = tid & 15;
    const int li   = tid * 4;
    const int srow = li >> 4;
    const int skk  = li & 15;

    float acc[4][4] = {};

    for (int kc = 0; kc < HID; kc += 16) {
        __syncthreads();
        float4 va = ldcg_f32x4(g_h1 + (rb + srow) * HID + kc + skk);
        sA[skk + 0][srow] = va.x; sA[skk + 1][srow] = va.y;
        sA[skk + 2][srow] = va.z; sA[skk + 3][srow] = va.w;
        float4 vb = *(const float4*)(w_lin + (size_t)srow * HID + kc + skk);
        sB[skk + 0][srow] = vb.x; sB[skk + 1][srow] = vb.y;
        sB[skk + 2][srow] = vb.z; sB[skk + 3][srow] = vb.w;
        __syncthreads();
        #pragma unroll
        for (int kk = 0; kk < 16; ++kk) {
            float4 a = *(const float4*)&sA[kk][ty * 4];
            float4 b = *(const float4*)&sB[kk][tx * 4];
            acc[0][0] = fmaf(a.x, b.x, acc[0][0]); acc[0][1] = fmaf(a.x, b.y, acc[0][1]);
            acc[0][2] = fmaf(a.x, b.z, acc[0][2]); acc[0][3] = fmaf(a.x, b.w, acc[0][3]);
            acc[1][0] = fmaf(a.y, b.x, acc[1][0]); acc[1][1] = fmaf(a.y, b.y, acc[1][1]);
            acc[1][2] = fmaf(a.y, b.z, acc[1][2]); acc[1][3] = fmaf(a.y, b.w, acc[1][3]);
            acc[2][0] = fmaf(a.z, b.x, acc[2][0]); acc[2][1] = fmaf(a.z, b.y, acc[2][1]);
            acc[2][2] = fmaf(a.z, b.z, acc[2][2]); acc[2][3] = fmaf(a.z, b.w, acc[2][3]);
            acc[3][0] = fmaf(a.w, b.x, acc[3][0]); acc[3][1] = fmaf(a.w, b.y, acc[3][1]);
            acc[3][2] = fmaf(a.w, b.z, acc[3][2]); acc[3][3] = fmaf(a.w, b.w, acc[3][3]);
        }
    }

    #pragma unroll
    for (int i = 0; i < 4; ++i) {
        float4 o4;
        o4.x = acc[i][0] + b_lin[tx * 4 + 0];
        o4.y = acc[i][1] + b_lin[tx * 4 + 1];
        o4.z = acc[i][2] + b_lin[tx * 4 + 2];
        o4.w = acc[i][3] + b_lin[tx * 4 + 3];
        *(float4*)(out + (rb + ty * 4 + i) * OUT_DIM + tx * 4) = o4;
    }
}

extern "C" void kernel_launch(void* const* d_in, const int* in_sizes, int n_in,
                              void* d_out, int out_size)
{
    const float* x     = (const float*)d_in[0];
    const float* w_ih0 = (const float*)d_in[1];
    const float* w_hh0 = (const float*)d_in[2];
    const float* b_ih0 = (const float*)d_in[3];
    const float* b_hh0 = (const float*)d_in[4];
    const float* w_ih1 = (const float*)d_in[5];
    const float* w_hh1 = (const float*)d_in[6];
    const float* b_ih1 = (const float*)d_in[7];
    const float* b_hh1 = (const float*)d_in[8];
    const float* w_lin = (const float*)d_in[9];
    const float* b_lin = (const float*)d_in[10];
    float* out = (float*)d_out;
    (void)in_sizes; (void)n_in; (void)out_size;

    float *gi_ptr;
    cudaGetSymbolAddress((void**)&gi_ptr, g_gi);

    cudaFuncSetAttribute(gru_rec_mma, cudaFuncAttributeMaxDynamicSharedMemorySize, SMEM_TOT);
    cudaFuncSetAttribute(gemm_bf16_3s, cudaFuncAttributeMaxDynamicSharedMemorySize, 4 * GST);

    // w_ih1 transpose + split (independent of layer 0)
    conv_w<<<dim3(HID / 32, GATES / 32), 256>>>(w_ih1);

    // layer 0
    gemm_tn_f32x2<<<dim3(GATES / 128, MROWS / 128), 256>>>(x, w_ih0, gi_ptr,
                                                           MROWS, GATES, IN_DIM);
    gru_rec_mma<<<NBLK, RTHR, SMEM_TOT>>>(w_hh0, b_ih0, b_hh0);

    // layer 1
    gemm_bf16_3s<<<dim3(GATES / 256, MROWS / 128), 512, 4 * GST>>>(gi_ptr);
    gru_rec_mma<<<NBLK, RTHR, SMEM_TOT>>>(w_hh1, b_ih1, b_hh1);

    // time-distributed linear
    out_linear<<<MROWS / 64, 256>>>(w_lin, b_lin, out);
}

// round 16
// speedup vs baseline: 1.3800x; 1.0804x over previous
#include <cuda_runtime.h>
#include <cuda_bf16.h>
#include <math.h>
#include <stdint.h>

#define T_STEPS 512
#define BATCH   128
#define IN_DIM  64
#define HID     1024
#define OUT_DIM 64
#define GATES   (3 * HID)
#define MROWS   (T_STEPS * BATCH)   // 65536
#define NBLK    128
#define RTHR    512

typedef unsigned long long u64;

// Persistent scratch (device globals -- no allocation anywhere).
__device__ float g_gi[(size_t)MROWS * GATES];        // input-side gates
__device__ float g_h1[(size_t)MROWS * HID];          // layer outputs (fp32)
__device__ __nv_bfloat16 g_h1hi[(size_t)MROWS * HID];// layer outputs, bf16 hi plane
__device__ __nv_bfloat16 g_h1lo[(size_t)MROWS * HID];// layer outputs, bf16 lo plane
__device__ __nv_bfloat16 g_hzero[BATCH * HID];       // zeros (h_{-1})
__device__ __nv_bfloat16 g_wbhi[(size_t)HID * GATES];// w_ih1^T [k][n] hi
__device__ __nv_bfloat16 g_wblo[(size_t)HID * GATES];// lo
__device__ __nv_bfloat16 g_w0hi[(size_t)IN_DIM * GATES]; // w_ih0^T [k][n] hi
__device__ __nv_bfloat16 g_w0lo[(size_t)IN_DIM * GATES]; // lo
__device__ __nv_bfloat16 g_xhi[(size_t)MROWS * IN_DIM];  // x hi plane
__device__ __nv_bfloat16 g_xlo[(size_t)MROWS * IN_DIM];  // x lo plane
__device__ unsigned g_bar_gen;
__device__ unsigned g_bar_cnt;

// ---------- helpers ----------
__device__ __forceinline__ float4 ldcg_f32x4(const void* p) {
    float4 v;
    asm volatile("ld.global.cg.v4.f32 {%0, %1, %2, %3}, [%4];"
                 : "=f"(v.x), "=f"(v.y), "=f"(v.z), "=f"(v.w) : "l"(p));
    return v;
}
__device__ __forceinline__ float ldcg_f32(const void* p) {
    float v;
    asm volatile("ld.global.cg.f32 %0, [%1];" : "=f"(v) : "l"(p));
    return v;
}
__device__ __forceinline__ void cp16(unsigned d, const void* s) {
    asm volatile("cp.async.cg.shared.global [%0], [%1], 16;" :: "r"(d), "l"(s));
}
__device__ __forceinline__ void ldsm4(uint32_t* r, uint32_t a) {
    asm volatile("ldmatrix.sync.aligned.m8n8.x4.shared.b16 {%0,%1,%2,%3}, [%4];"
                 : "=r"(r[0]), "=r"(r[1]), "=r"(r[2]), "=r"(r[3]) : "r"(a));
}
__device__ __forceinline__ void ldsm2t(uint32_t* r, uint32_t a) {
    asm volatile("ldmatrix.sync.aligned.m8n8.x2.trans.shared.b16 {%0,%1}, [%2];"
                 : "=r"(r[0]), "=r"(r[1]) : "r"(a));
}
__device__ __forceinline__ void mma16816(float* c, const uint32_t* a, const uint32_t* b) {
    asm volatile("mma.sync.aligned.m16n8k16.row.col.f32.bf16.bf16.f32 "
                 "{%0,%1,%2,%3}, {%4,%5,%6,%7}, {%8,%9}, {%0,%1,%2,%3};"
                 : "+f"(c[0]), "+f"(c[1]), "+f"(c[2]), "+f"(c[3])
                 : "r"(a[0]), "r"(a[1]), "r"(a[2]), "r"(a[3]), "r"(b[0]), "r"(b[1]));
}
// swizzles (byte-offset XOR)
__device__ __forceinline__ uint32_t SWA(uint32_t a) { return a ^ ((a >> 3) & 0x10); }   // 32B rows
__device__ __forceinline__ uint32_t SW128(uint32_t a){ return a ^ ((a >> 3) & 0x70); }  // 128B rows
__device__ __forceinline__ uint32_t SWR(int row, uint32_t c) { return c ^ (((uint32_t)row & 7u) << 4); }

// ---- grid barrier: release/acquire, nanosleep poll ----
__device__ __forceinline__ void grid_bar() {
    __syncthreads();
    if (threadIdx.x == 0) {
        unsigned gen;
        asm volatile("ld.global.relaxed.gpu.u32 %0, [%1];"
                     : "=r"(gen) : "l"(&g_bar_gen));
        asm volatile("fence.acq_rel.gpu;" ::: "memory");
        unsigned prev = atomicAdd(&g_bar_cnt, 1u);
        if (prev == (unsigned)(NBLK - 1)) {
            asm volatile("st.global.relaxed.gpu.u32 [%0], %1;"
                         :: "l"(&g_bar_cnt), "r"(0u) : "memory");
            asm volatile("fence.acq_rel.gpu;" ::: "memory");
            asm volatile("st.global.relaxed.gpu.u32 [%0], %1;"
                         :: "l"(&g_bar_gen), "r"(gen + 1u) : "memory");
        } else {
            unsigned cur;
            do {
                __nanosleep(64);
                asm volatile("ld.global.relaxed.gpu.u32 %0, [%1];"
                             : "=r"(cur) : "l"(&g_bar_gen));
            } while (cur == gen);
            asm volatile("fence.acq_rel.gpu;" ::: "memory");
        }
    }
    __syncthreads();
}

// rec smem layout (bytes)
#define SMEM_BIAS 0
#define SMEM_W    1024                   // W hi: [1024k][24n] bf16, 48B rows = 48 KB
#define SMEM_WLO  (1024 + 49152)         // 50176
#define SMEM_ACT  (50176 + 49152)        // 99328: 2 slots x 64 KB (128-k chunks)
#define SLOT      65536                  // [2 sub(64k)][2 pl][128 rows][128 B], SW128
#define SMEM_TOT  (99328 + 2 * SLOT)     // 230,400 B
// red buffer (48 KB) aliases SMEM_ACT after the k-loop.

// ============================================================================
// GRU recurrence on mma.sync. 8 chunks of 128 k (2x 64-k SW128 sub-buffers),
// ring 2, single sync per chunk:
//   { ldsm B(i); wait_group 0; __syncthreads(); stage(i+1); compute(i) }
// Safe: stage(i+1) overwrites chunk i-1's slot, last read in compute(i-1),
// which precedes this iteration's sync for every warp.
// Warp (p=w&3, q=w>>2): m [32p,32p+32) x n24, k16-tiles {2q, 2q+1} per chunk.
// ============================================================================
__global__ void __launch_bounds__(RTHR, 1)
gru_rec_mma(const float* __restrict__ w_hh, const float* __restrict__ b_ih,
            const float* __restrict__ b_hh)
{
    extern __shared__ char smem[];
    const int tid  = threadIdx.x;
    const int wid  = tid >> 5;
    const int lane = tid & 31;
    const int bid  = blockIdx.x;
    const int j0   = bid * 8;
    const int p    = wid & 3;
    const int q    = wid >> 2;
    const uint32_t sb = (uint32_t)__cvta_generic_to_shared(smem);

    for (int idx = tid; idx < 24 * HID; idx += RTHR) {
        int n = idx >> 10, k = idx & 1023;
        float w = w_hh[((size_t)(n >> 3) * HID + j0 + (n & 7)) * HID + k];
        __nv_bfloat16 hi = __float2bfloat16(w);
        __nv_bfloat16 lo = __float2bfloat16(w - __bfloat162float(hi));
        uint32_t a = (uint32_t)(k * 48 + n * 2);
        *(__nv_bfloat16*)(smem + SMEM_W   + a) = hi;
        *(__nv_bfloat16*)(smem + SMEM_WLO + a) = lo;
    }
    if (tid < 8) {
        float* sB = (float*)(smem + SMEM_BIAS);
        int j = j0 + tid;
        sB[tid]      = b_ih[j] + b_hh[j];
        sB[8 + tid]  = b_ih[HID + j] + b_hh[HID + j];
        sB[16 + tid] = b_ih[2 * HID + j];
        sB[24 + tid] = b_hh[2 * HID + j];
    }
    for (int idx = bid * RTHR + tid; idx < BATCH * HID; idx += NBLK * RTHR)
        g_hzero[idx] = __float2bfloat16(0.0f);
    __syncthreads();
    grid_bar();

    const int relrow = ((lane >> 3) & 1) * 8 + (lane & 7);
    const int segA   = lane >> 4;
    // A fragment offsets per s (k16 tile kt = 2q+s): sub = kt>>2, idx = kt&3
    uint32_t offAm[2][2];   // [s][mt]
    #pragma unroll
    for (int s = 0; s < 2; ++s) {
        int kt  = q * 2 + s;
        uint32_t sub = (uint32_t)((kt >> 2) * 32768);
        uint32_t idx = (uint32_t)((kt & 3) * 32);
        offAm[s][0] = sub + SW128((uint32_t)((32 * p + relrow) * 128) + idx + segA * 16);
        offAm[s][1] = sub + SW128((uint32_t)((32 * p + 16 + relrow) * 128) + idx + segA * 16);
    }
    const int rbB = lane & 15;
    // coalesced staging map: 8 lanes per 128B row segment; 8 cp16/thread/chunk
    const int spl   = tid >> 8;
    const int sidx  = tid & 255;
    const int srow0 = sidx >> 3;
    const int scol  = (sidx & 7) * 16;
    const int selm  = (sidx & 7) * 8;
    const int eu = tid & 7;
    const int em = tid >> 3;

    for (int t = 0; t < T_STEPS; ++t) {
        const __nv_bfloat16* hi_src = t ? g_h1hi + (size_t)(t - 1) * BATCH * HID : g_hzero;
        const __nv_bfloat16* lo_src = t ? g_h1lo + (size_t)(t - 1) * BATCH * HID : g_hzero;
        const __nv_bfloat16* splane = spl ? lo_src : hi_src;

        // prologue: stage chunk 0 into slot 0
        {
            uint32_t bb = sb + SMEM_ACT + (uint32_t)(spl * 16384);
            #pragma unroll
            for (int sub = 0; sub < 2; ++sub)
                #pragma unroll
                for (int s4 = 0; s4 < 4; ++s4) {
                    int row = srow0 + s4 * 32;
                    cp16(bb + (uint32_t)(sub * 32768) + SW128((uint32_t)(row * 128 + scol)),
                         splane + (size_t)row * HID + sub * 64 + selm);
                }
            asm volatile("cp.async.commit_group;");
        }

        float gir[2], giz[2], gin[2], hpv[2];
        #pragma unroll
        for (int it = 0; it < 2; ++it) {
            int m = em + it * 64;
            const float* gp = g_gi + ((size_t)t * BATCH + m) * GATES + j0 + eu;
            gir[it] = ldcg_f32(gp);
            giz[it] = ldcg_f32(gp + HID);
            gin[it] = ldcg_f32(gp + 2 * HID);
            hpv[it] = t ? ldcg_f32(g_h1 + ((size_t)(t - 1) * BATCH + m) * HID + j0 + eu)
                        : 0.0f;
        }

        float c[2][3][4];
        #pragma unroll
        for (int mt = 0; mt < 2; ++mt)
            #pragma unroll
            for (int g = 0; g < 3; ++g)
                #pragma unroll
                for (int x = 0; x < 4; ++x) c[mt][g][x] = 0.0f;

        #pragma unroll 1
        for (int i = 0; i < 8; ++i) {
            // B fragments for both k16 tiles of chunk i (persistent W)
            uint32_t bh[2][3][2], bl[2][3][2];
            #pragma unroll
            for (int s = 0; s < 2; ++s) {
                const int kb = i * 128 + (q * 2 + s) * 16;
                #pragma unroll
                for (int g = 0; g < 3; ++g) {
                    uint32_t a = (uint32_t)((kb + rbB) * 48 + g * 16);
                    ldsm2t(bh[s][g], sb + SMEM_W + a);
                    ldsm2t(bl[s][g], sb + SMEM_WLO + a);
                }
            }

            asm volatile("cp.async.wait_group 0;");   // chunk i arrived
            __syncthreads();                          // publish + guard reuse

            if (i + 1 < 8) {   // stage chunk i+1 into the other slot
                uint32_t bb = sb + SMEM_ACT
                            + (uint32_t)(((i + 1) & 1) * SLOT + spl * 16384);
                #pragma unroll
                for (int sub = 0; sub < 2; ++sub)
                    #pragma unroll
                    for (int s4 = 0; s4 < 4; ++s4) {
                        int row = srow0 + s4 * 32;
                        cp16(bb + (uint32_t)(sub * 32768) + SW128((uint32_t)(row * 128 + scol)),
                             splane + (size_t)row * HID + (i + 1) * 128 + sub * 64 + selm);
                    }
                asm volatile("cp.async.commit_group;");
            }

            const uint32_t abase = sb + SMEM_ACT + (uint32_t)((i & 1) * SLOT);
            #pragma unroll
            for (int s = 0; s < 2; ++s) {
                #pragma unroll
                for (int mt = 0; mt < 2; ++mt) {
                    uint32_t ah[4], al[4];
                    ldsm4(ah, abase + offAm[s][mt]);
                    ldsm4(al, abase + 16384 + offAm[s][mt]);
                    #pragma unroll
                    for (int g = 0; g < 3; ++g) {
                        mma16816(c[mt][g], ah, bh[s][g]);
                        mma16816(c[mt][g], al, bh[s][g]);
                        mma16816(c[mt][g], ah, bl[s][g]);
                    }
                }
            }
        }

        __syncthreads();
        float* red = (float*)(smem + SMEM_ACT);   // [128 m][24 n][4 q]
        {
            const int rr0 = p * 32 + (lane >> 2);
            const int c2  = (lane & 3) * 2;
            #pragma unroll
            for (int mt = 0; mt < 2; ++mt) {
                int rr = rr0 + mt * 16;
                #pragma unroll
                for (int g = 0; g < 3; ++g) {
                    int nn = g * 8 + c2;
                    red[(rr * 24 + nn) * 4 + q]           = c[mt][g][0];
                    red[(rr * 24 + nn + 1) * 4 + q]       = c[mt][g][1];
                    red[((rr + 8) * 24 + nn) * 4 + q]     = c[mt][g][2];
                    red[((rr + 8) * 24 + nn + 1) * 4 + q] = c[mt][g][3];
                }
            }
        }
        __syncthreads();

        {
            const float* sB = (const float*)(smem + SMEM_BIAS);
            #pragma unroll
            for (int it = 0; it < 2; ++it) {
                int m = em + it * 64;
                float4 vr = *(const float4*)(red + ((size_t)m * 24 + eu) * 4);
                float4 vz = *(const float4*)(red + ((size_t)m * 24 + 8 + eu) * 4);
                float4 vn = *(const float4*)(red + ((size_t)m * 24 + 16 + eu) * 4);
                float ghr = (vr.x + vr.y) + (vr.z + vr.w);
                float ghz = (vz.x + vz.y) + (vz.z + vz.w);
                float ghn = (vn.x + vn.y) + (vn.z + vn.w);
                float rg = 1.0f / (1.0f + expf(-(gir[it] + ghr + sB[eu])));
                float zg = 1.0f / (1.0f + expf(-(giz[it] + ghz + sB[8 + eu])));
                float ng = tanhf(gin[it] + sB[16 + eu] + rg * (ghn + sB[24 + eu]));
                float h  = (1.0f - zg) * ng + zg * hpv[it];

                __nv_bfloat16 hi = __float2bfloat16(h);
                __nv_bfloat16 lo = __float2bfloat16(h - __bfloat162float(hi));
                size_t o = ((size_t)t * BATCH + m) * HID + j0 + eu;
                g_h1hi[o] = hi;
                g_h1lo[o] = lo;
                g_h1[o]   = h;
            }
        }

        grid_bar();
    }
}

// ============================================================================
// Transpose + bf16-split weight: [3072 n][K k] fp32 -> [k][n] hi/lo planes.
// ============================================================================
__global__ void __launch_bounds__(256)
conv_w(const float* __restrict__ w, __nv_bfloat16* __restrict__ whi,
       __nv_bfloat16* __restrict__ wlo, int K)
{
    __shared__ float tile[32][33];
    const int tx = threadIdx.x & 31;
    const int ty = threadIdx.x >> 5;
    const int k0 = blockIdx.x * 32;
    const int n0 = blockIdx.y * 32;
    #pragma unroll
    for (int r = 0; r < 4; ++r)
        tile[ty + r * 8][tx] = w[(size_t)(n0 + ty + r * 8) * K + k0 + tx];
    __syncthreads();
    #pragma unroll
    for (int r = 0; r < 4; ++r) {
        float v = tile[tx][ty + r * 8];
        __nv_bfloat16 hi = __float2bfloat16(v);
        __nv_bfloat16 lo = __float2bfloat16(v - __bfloat162float(hi));
        size_t o = (size_t)(k0 + ty + r * 8) * GATES + n0 + tx;
        whi[o] = hi;
        wlo[o] = lo;
    }
}

// elementwise fp32 -> bf16 hi/lo split
__global__ void __launch_bounds__(256)
conv_split(const float* __restrict__ src, __nv_bfloat16* __restrict__ hi,
           __nv_bfloat16* __restrict__ lo, int n4)
{
    int i = blockIdx.x * 256 + threadIdx.x;
    if (i >= n4) return;
    float4 v = *(const float4*)(src + (size_t)i * 4);
    float vv[4] = {v.x, v.y, v.z, v.w};
    __nv_bfloat16 h4[4], l4[4];
    #pragma unroll
    for (int j = 0; j < 4; ++j) {
        h4[j] = __float2bfloat16(vv[j]);
        l4[j] = __float2bfloat16(vv[j] - __bfloat162float(h4[j]));
    }
    *(uint2*)(hi + (size_t)i * 4) = *(uint2*)h4;
    *(uint2*)(lo + (size_t)i * 4) = *(uint2*)l4;
}

// ============================================================================
// C[M,3072] = A @ B^T on mma.sync (bf16 3-split). Tile 128m x 256n.
// A: hi/lo planes, row stride astr; B: [k][3072] hi/lo planes. nch = K/16.
// Ring 4, distance 2, single sync per chunk.
// ============================================================================
#define GST 24576
__global__ void __launch_bounds__(512)
gemm_bf16_3s(float* __restrict__ C,
             const __nv_bfloat16* __restrict__ Ahip, const __nv_bfloat16* __restrict__ Alop,
             int astr,
             const __nv_bfloat16* __restrict__ Bhip, const __nv_bfloat16* __restrict__ Blop,
             int nch)
{
    extern __shared__ char gsm[];   // 4 * 24576
    const int tid  = threadIdx.x;
    const int wid  = tid >> 5;
    const int lane = tid & 31;
    const int m0 = blockIdx.y * 128;
    const int n0 = blockIdx.x * 256;
    const int p  = wid & 3;
    const int nq = wid >> 2;
    const uint32_t sb = (uint32_t)__cvta_generic_to_shared(gsm);

    const int relrow = ((lane >> 3) & 1) * 8 + (lane & 7);
    const int segA   = lane >> 4;
    const uint32_t offA0 = SWA((uint32_t)((p * 32 + relrow) * 32 + segA * 16));
    const uint32_t offA1 = SWA((uint32_t)((p * 32 + 16 + relrow) * 32 + segA * 16));
    const int rbB = lane & 15;
    uint32_t offB[8];
    #pragma unroll
    for (int nt = 0; nt < 8; ++nt)
        offB[nt] = (uint32_t)(8192 + rbB * 512) + SWR(rbB, (uint32_t)(nq * 128 + nt * 16));

    const bool stA = (tid < 256);
    const int  apl = (tid >> 7) & 1;
    const int  am  = tid & 127;
    const int  bix = tid & 255;
    const int  bpl = bix >> 7;
    const int  bsub = bix & 127;
    const int  brw  = bsub >> 3;
    const int  bcb  = (bsub & 7) * 64;

    const __nv_bfloat16* Asrc = (apl ? Alop : Ahip) + (size_t)(m0 + am) * astr;
    const __nv_bfloat16* Bsrc = (bpl ? Blop : Bhip) + n0 + bcb / 2;
    const uint32_t adst0 = (uint32_t)(apl * 4096) + SWA((uint32_t)(am * 32));
    const uint32_t adst1 = (uint32_t)(apl * 4096) + SWA((uint32_t)(am * 32 + 16));
    uint32_t bdst[4];
    #pragma unroll
    for (int jj = 0; jj < 4; ++jj)
        bdst[jj] = (uint32_t)(8192 + bpl * 8192 + brw * 512)
                 + SWR(brw, (uint32_t)(bcb + jj * 16));

    float c[2][8][4];
    #pragma unroll
    for (int mt = 0; mt < 2; ++mt)
        #pragma unroll
        for (int nt = 0; nt < 8; ++nt)
            #pragma unroll
            for (int x = 0; x < 4; ++x) c[mt][nt][x] = 0.0f;

    #pragma unroll
    for (int pre = 0; pre < 2; ++pre) {
        uint32_t base = sb + (uint32_t)(pre * GST);
        if (stA) {
            cp16(base + adst0, Asrc + pre * 16);
            cp16(base + adst1, Asrc + pre * 16 + 8);
        } else {
            const __nv_bfloat16* s = Bsrc + (size_t)(pre * 16 + brw) * GATES;
            #pragma unroll
            for (int jj = 0; jj < 4; ++jj)
                cp16(base + bdst[jj], s + jj * 8);
        }
        asm volatile("cp.async.commit_group;");
    }

    #pragma unroll 1
    for (int i = 0; i < nch; ++i) {
        if (i + 2 < nch) {
            uint32_t base = sb + (uint32_t)(((i + 2) & 3) * GST);
            if (stA) {
                cp16(base + adst0, Asrc + (i + 2) * 16);
                cp16(base + adst1, Asrc + (i + 2) * 16 + 8);
            } else {
                const __nv_bfloat16* s = Bsrc + (size_t)((i + 2) * 16 + brw) * GATES;
                #pragma unroll
                for (int jj = 0; jj < 4; ++jj)
                    cp16(base + bdst[jj], s + jj * 8);
            }
            asm volatile("cp.async.commit_group;");
            asm volatile("cp.async.wait_group 2;");
        } else {
            asm volatile("cp.async.wait_group 0;");
        }
        __syncthreads();

        const uint32_t base = sb + (uint32_t)((i & 3) * GST);
        uint32_t ah[2][4], al[2][4];
        ldsm4(ah[0], base + offA0);
        ldsm4(ah[1], base + offA1);
        ldsm4(al[0], base + 4096 + offA0);
        ldsm4(al[1], base + 4096 + offA1);
        #pragma unroll
        for (int nt = 0; nt < 8; ++nt) {
            uint32_t bh[2], blv[2];
            ldsm2t(bh, base + offB[nt]);
            ldsm2t(blv, base + offB[nt] + 8192);
            #pragma unroll
            for (int mt = 0; mt < 2; ++mt) {
                mma16816(c[mt][nt], ah[mt], bh);
                mma16816(c[mt][nt], al[mt], bh);
                mma16816(c[mt][nt], ah[mt], blv);
            }
        }
    }

    #pragma unroll
    for (int mt = 0; mt < 2; ++mt) {
        int row = m0 + p * 32 + mt * 16 + (lane >> 2);
        #pragma unroll
        for (int nt = 0; nt < 8; ++nt) {
            int col = n0 + nq * 64 + nt * 8 + (lane & 3) * 2;
            *(float2*)(C + (size_t)row * GATES + col) =
                make_float2(c[mt][nt][0], c[mt][nt][1]);
            *(float2*)(C + (size_t)(row + 8) * GATES + col) =
                make_float2(c[mt][nt][2], c[mt][nt][3]);
        }
    }
}

// ============================================================================
// out[t,b,o] = h2[t,b,:] . w_lin[o,:] + b_lin[o]  (h2 in g_h1)
// ============================================================================
__global__ void __launch_bounds__(256)
out_linear(const float* __restrict__ w_lin, const float* __restrict__ b_lin,
           float* __restrict__ out)
{
    __shared__ float sA[16][68];
    __shared__ float sB[16][68];
    const int tid = threadIdx.x;
    const size_t rb = (size_t)blockIdx.x * 64;
    const int ty = tid >> 4;
    const int tx = tid & 15;
    const int li   = tid * 4;
    const int srow = li >> 4;
    const int skk  = li & 15;

    float acc[4][4] = {};

    for (int kc = 0; kc < HID; kc += 16) {
        __syncthreads();
        float4 va = ldcg_f32x4(g_h1 + (rb + srow) * HID + kc + skk);
        sA[skk + 0][srow] = va.x; sA[skk + 1][srow] = va.y;
        sA[skk + 2][srow] = va.z; sA[skk + 3][srow] = va.w;
        float4 vb = *(const float4*)(w_lin + (size_t)srow * HID + kc + skk);
        sB[skk + 0][srow] = vb.x; sB[skk + 1][srow] = vb.y;
        sB[skk + 2][srow] = vb.z; sB[skk + 3][srow] = vb.w;
        __syncthreads();
        #pragma unroll
        for (int kk = 0; kk < 16; ++kk) {
            float4 a = *(const float4*)&sA[kk][ty * 4];
            float4 b = *(const float4*)&sB[kk][tx * 4];
            acc[0][0] = fmaf(a.x, b.x, acc[0][0]); acc[0][1] = fmaf(a.x, b.y, acc[0][1]);
            acc[0][2] = fmaf(a.x, b.z, acc[0][2]); acc[0][3] = fmaf(a.x, b.w, acc[0][3]);
            acc[1][0] = fmaf(a.y, b.x, acc[1][0]); acc[1][1] = fmaf(a.y, b.y, acc[1][1]);
            acc[1][2] = fmaf(a.y, b.z, acc[1][2]); acc[1][3] = fmaf(a.y, b.w, acc[1][3]);
            acc[2][0] = fmaf(a.z, b.x, acc[2][0]); acc[2][1] = fmaf(a.z, b.y, acc[2][1]);
            acc[2][2] = fmaf(a.z, b.z, acc[2][2]); acc[2][3] = fmaf(a.z, b.w, acc[2][3]);
            acc[3][0] = fmaf(a.w, b.x, acc[3][0]); acc[3][1] = fmaf(a.w, b.y, acc[3][1]);
            acc[3][2] = fmaf(a.w, b.z, acc[3][2]); acc[3][3] = fmaf(a.w, b.w, acc[3][3]);
        }
    }

    #pragma unroll
    for (int i = 0; i < 4; ++i) {
        float4 o4;
        o4.x = acc[i][0] + b_lin[tx * 4 + 0];
        o4.y = acc[i][1] + b_lin[tx * 4 + 1];
        o4.z = acc[i][2] + b_lin[tx * 4 + 2];
        o4.w = acc[i][3] + b_lin[tx * 4 + 3];
        *(float4*)(out + (rb + ty * 4 + i) * OUT_DIM + tx * 4) = o4;
    }
}

extern "C" void kernel_launch(void* const* d_in, const int* in_sizes, int n_in,
                              void* d_out, int out_size)
{
    const float* x     = (const float*)d_in[0];
    const float* w_ih0 = (const float*)d_in[1];
    const float* w_hh0 = (const float*)d_in[2];
    const float* b_ih0 = (const float*)d_in[3];
    const float* b_hh0 = (const float*)d_in[4];
    const float* w_ih1 = (const float*)d_in[5];
    const float* w_hh1 = (const float*)d_in[6];
    const float* b_ih1 = (const float*)d_in[7];
    const float* b_hh1 = (const float*)d_in[8];
    const float* w_lin = (const float*)d_in[9];
    const float* b_lin = (const float*)d_in[10];
    float* out = (float*)d_out;
    (void)in_sizes; (void)n_in; (void)out_size;

    float *gi_ptr;
    cudaGetSymbolAddress((void**)&gi_ptr, g_gi);
    __nv_bfloat16 *h1hi, *h1lo, *wbhi, *wblo, *w0hi, *w0lo, *xhi, *xlo;
    cudaGetSymbolAddress((void**)&h1hi, g_h1hi);
    cudaGetSymbolAddress((void**)&h1lo, g_h1lo);
    cudaGetSymbolAddress((void**)&wbhi, g_wbhi);
    cudaGetSymbolAddress((void**)&wblo, g_wblo);
    cudaGetSymbolAddress((void**)&w0hi, g_w0hi);
    cudaGetSymbolAddress((void**)&w0lo, g_w0lo);
    cudaGetSymbolAddress((void**)&xhi, g_xhi);
    cudaGetSymbolAddress((void**)&xlo, g_xlo);

    cudaFuncSetAttribute(gru_rec_mma, cudaFuncAttributeMaxDynamicSharedMemorySize, SMEM_TOT);
    cudaFuncSetAttribute(gemm_bf16_3s, cudaFuncAttributeMaxDynamicSharedMemorySize, 4 * GST);

    // weight / input conversions (independent of recurrences)
    conv_w<<<dim3(HID / 32, GATES / 32), 256>>>(w_ih1, wbhi, wblo, HID);
    conv_w<<<dim3(IN_DIM / 32, GATES / 32), 256>>>(w_ih0, w0hi, w0lo, IN_DIM);
    conv_split<<<(MROWS * IN_DIM / 4 + 255) / 256, 256>>>(x, xhi, xlo, MROWS * IN_DIM / 4);

    // layer 0: gi0 = x @ w_ih0^T (bf16 3-split), then recurrence
    gemm_bf16_3s<<<dim3(GATES / 256, MROWS / 128), 512, 4 * GST>>>(
        gi_ptr, xhi, xlo, IN_DIM, w0hi, w0lo, IN_DIM / 16);
    gru_rec_mma<<<NBLK, RTHR, SMEM_TOT>>>(w_hh0, b_ih0, b_hh0);

    // layer 1: gi1 = h1 @ w_ih1^T, then recurrence
    gemm_bf16_3s<<<dim3(GATES / 256, MROWS / 128), 512, 4 * GST>>>(
        gi_ptr, h1hi, h1lo, HID, wbhi, wblo, HID / 16);
    gru_rec_mma<<<NBLK, RTHR, SMEM_TOT>>>(w_hh1, b_ih1, b_hh1);

    // time-distributed linear
    out_linear<<<MROWS / 64, 256>>>(w_lin, b_lin, out);
}